// round 7
// baseline (speedup 1.0000x reference)
#include <cuda_runtime.h>
#include <cuda_bf16.h>
#include <cstdint>

#define BATCH 4
#define SEQ   4096
#define DIM   768
#define NTOK  (BATCH*SEQ)

// ---------------- scratch (__device__ globals: allocation-free rule) --------
__device__ __nv_bfloat16 g_Xhi [(size_t)NTOK * DIM];
__device__ __nv_bfloat16 g_Xlo [(size_t)NTOK * DIM];
__device__ __nv_bfloat16 g_WThi[3ull * DIM * DIM];
__device__ __nv_bfloat16 g_WTlo[3ull * DIM * DIM];
__device__ __nv_bfloat16 g_Qhi [(size_t)NTOK * DIM];
__device__ __nv_bfloat16 g_Qlo [(size_t)NTOK * DIM];
__device__ __nv_bfloat16 g_Khi [(size_t)NTOK * DIM];
__device__ __nv_bfloat16 g_Klo [(size_t)NTOK * DIM];
__device__ __nv_bfloat16 g_Vhi [(size_t)NTOK * DIM];
__device__ __nv_bfloat16 g_Vlo [(size_t)NTOK * DIM];
__device__ __nv_bfloat16 g_VThi[(size_t)BATCH * DIM * SEQ];
__device__ __nv_bfloat16 g_VTlo[(size_t)BATCH * DIM * SEQ];
__device__ __nv_bfloat16 g_Phi [(size_t)BATCH * SEQ * SEQ];   // exp(scores) hi
__device__ __nv_bfloat16 g_Plo [(size_t)BATCH * SEQ * SEQ];   // exp(scores) lo
__device__ float g_partial[(size_t)NTOK * 16];                // per-(row,256tile) sums
__device__ float g_rowsum [(size_t)NTOK];                     // final row sums

// ---------------- PTX helpers (arch-agnostic, sm_80-class) ------------------
__device__ __forceinline__ uint32_t smem_u32(const void* p) {
    uint32_t a;
    asm("{ .reg .u64 t; cvta.to.shared.u64 t, %1; cvt.u32.u64 %0, t; }"
        : "=r"(a) : "l"(p));
    return a;
}
__device__ __forceinline__ void cp16(uint32_t dst, const void* src) {
    asm volatile("cp.async.cg.shared.global [%0], [%1], 16;"
                 :: "r"(dst), "l"(src) : "memory");
}
#define CP_COMMIT() asm volatile("cp.async.commit_group;" ::: "memory")
#define CP_WAIT(N)  asm volatile("cp.async.wait_group %0;" :: "n"(N) : "memory")

__device__ __forceinline__ void ldsm_x4(uint32_t* r, uint32_t addr) {
    asm volatile("ldmatrix.sync.aligned.m8n8.x4.shared.b16 {%0,%1,%2,%3}, [%4];"
                 : "=r"(r[0]), "=r"(r[1]), "=r"(r[2]), "=r"(r[3]) : "r"(addr));
}
__device__ __forceinline__ void mma16816(float* d, const uint32_t* a, const uint32_t* b) {
    asm volatile(
        "mma.sync.aligned.m16n8k16.row.col.f32.bf16.bf16.f32 "
        "{%0,%1,%2,%3}, {%4,%5,%6,%7}, {%8,%9}, {%0,%1,%2,%3};"
        : "+f"(d[0]), "+f"(d[1]), "+f"(d[2]), "+f"(d[3])
        : "r"(a[0]), "r"(a[1]), "r"(a[2]), "r"(a[3]), "r"(b[0]), "r"(b[1]));
}

// fp32 pair -> bf16 hi pair + bf16 lo pair (packed u32 each)
__device__ __forceinline__ void split2(float a, float b, uint32_t& h, uint32_t& l) {
    __nv_bfloat162 hv = __float22bfloat162_rn(make_float2(a, b));
    float2 f = __bfloat1622float2(hv);
    __nv_bfloat162 lv = __float22bfloat162_rn(make_float2(a - f.x, b - f.y));
    h = *reinterpret_cast<uint32_t*>(&hv);
    l = *reinterpret_cast<uint32_t*>(&lv);
}

// ---------------- pipelined GEMM core ----------------------------------------
// C[128,256] = A[128,K](hi+lo) * B[256,K](hi+lo)^T, bf16 MMA x3, fp32 accum.
// 256 threads (8 warps, 2m x 4n), warp tile 64x64, k-step 32,
// 3-stage cp.async ring, ONE CTA/SM, one barrier per iteration.
#define LDSE 40                        // smem row stride (bf16): conflict-free ldsm
#define A_BYTES (128 * LDSE * 2)       // 10240
#define B_BYTES (256 * LDSE * 2)       // 20480
#define STG_BYTES (2 * A_BYTES + 2 * B_BYTES)   // 61440
#define SMEM_BYTES (3 * STG_BYTES)              // 184320

#define SM_SCALE 0.03608439182435161f  // 1/sqrt(768)

// MODE 1: write split bf16 Chi/Clo (proj).
// MODE 2: exp + causal mask + per-row partial sums -> g_partial; split bf16 out.
// MODE 3: write fp32 C scaled by 1/g_rowsum[row] (pv).
template <int MODE>
__device__ __forceinline__ void gemm_pipe(
    const __nv_bfloat16* __restrict__ Ahi, const __nv_bfloat16* __restrict__ Alo, int lda,
    const __nv_bfloat16* __restrict__ Bhi, const __nv_bfloat16* __restrict__ Blo, int ldb,
    float* __restrict__ C, __nv_bfloat16* __restrict__ Chi, __nv_bfloat16* __restrict__ Clo,
    int ldc, int i0, int j0, int K, int rs_off)
{
    extern __shared__ __align__(16) uint16_t dsm[];
    const uint32_t sb = smem_u32(dsm);

    const int tid  = threadIdx.x;
    const int wid  = tid >> 5;
    const int lane = tid & 31;
    const int m0 = (wid & 1) * 64;       // warp row offset (2 m-warps)
    const int n0 = (wid >> 1) * 64;      // warp col offset (4 n-warps x 64)

    const int a_row = lane & 15;
    const int a_col = (lane >> 4) * 8;
    const int b_row = ((lane >> 4) & 1) * 8 + (lane & 7);
    const int b_col = ((lane >> 3) & 1) * 8;

    const int nk = K >> 5;

    auto stage = [&](int s, int kt) {
        const uint32_t base = sb + (uint32_t)(s * STG_BYTES);
        // A hi/lo: 128x32, 512 16B-chunks per buffer, 2 per thread
#pragma unroll
        for (int k = 0; k < 2; ++k) {
            int u = tid + k * 256;
            int r = u >> 2, c = (u & 3) * 8;
            uint32_t so = (uint32_t)(r * LDSE + c) * 2;
            cp16(base + so,           Ahi + (size_t)(i0 + r) * lda + kt + c);
            cp16(base + A_BYTES + so, Alo + (size_t)(i0 + r) * lda + kt + c);
        }
        // B hi/lo: 256x32, 1024 chunks per buffer, 4 per thread
#pragma unroll
        for (int k = 0; k < 4; ++k) {
            int u = tid + k * 256;
            int r = u >> 2, c = (u & 3) * 8;
            uint32_t so = (uint32_t)(r * LDSE + c) * 2;
            cp16(base + 2 * A_BYTES + so,           Bhi + (size_t)(j0 + r) * ldb + kt + c);
            cp16(base + 2 * A_BYTES + B_BYTES + so, Blo + (size_t)(j0 + r) * ldb + kt + c);
        }
        CP_COMMIT();
    };

    float acc[4][8][4] = {};

    stage(0, 0);
    if (nk > 1) stage(1, 32);
    for (int it = 0; it < nk; ++it) {
        const int s = it % 3;
        if (it + 1 < nk) { CP_WAIT(1); } else { CP_WAIT(0); }
        __syncthreads();
        if (it + 2 < nk) stage((it + 2) % 3, (it + 2) << 5);

        const uint32_t base = sb + (uint32_t)(s * STG_BYTES);
        const uint32_t bAhi = base;
        const uint32_t bAlo = base + A_BYTES;
        const uint32_t bBhi = base + 2 * A_BYTES;
        const uint32_t bBlo = base + 2 * A_BYTES + B_BYTES;

#pragma unroll
        for (int kk = 0; kk < 32; kk += 16) {
            uint32_t aH[4][4], aL[4][4];
#pragma unroll
            for (int mi = 0; mi < 4; ++mi) {
                uint32_t off = (uint32_t)((m0 + mi * 16 + a_row) * LDSE + kk + a_col) * 2;
                ldsm_x4(aH[mi], bAhi + off);
                ldsm_x4(aL[mi], bAlo + off);
            }
#pragma unroll
            for (int nj = 0; nj < 4; ++nj) {          // 4 x 16-n chunks = 64 n
                uint32_t off = (uint32_t)((n0 + nj * 16 + b_row) * LDSE + kk + b_col) * 2;
                uint32_t bh[4], bl[4];
                ldsm_x4(bh, bBhi + off);
                ldsm_x4(bl, bBlo + off);
#pragma unroll
                for (int mi = 0; mi < 4; ++mi) {
                    mma16816(acc[mi][nj * 2],     aH[mi], bh);
                    mma16816(acc[mi][nj * 2 + 1], aH[mi], bh + 2);
                    mma16816(acc[mi][nj * 2],     aH[mi], bl);
                    mma16816(acc[mi][nj * 2 + 1], aH[mi], bl + 2);
                    mma16816(acc[mi][nj * 2],     aL[mi], bh);
                    mma16816(acc[mi][nj * 2 + 1], aL[mi], bh + 2);
                }
            }
        }
    }

    // ---- epilogue ------------------------------------------------------------
    const int tr = lane >> 2;
    const int tc = (lane & 3) * 2;

    if (MODE == 1) {
#pragma unroll
        for (int mi = 0; mi < 4; ++mi)
#pragma unroll
            for (int nj = 0; nj < 8; ++nj) {
                int row = i0 + m0 + mi * 16 + tr;
                int col = j0 + n0 + nj * 8 + tc;
                uint32_t h, l;
                size_t idx = (size_t)row * ldc + col;
                split2(acc[mi][nj][0], acc[mi][nj][1], h, l);
                *reinterpret_cast<uint32_t*>(Chi + idx) = h;
                *reinterpret_cast<uint32_t*>(Clo + idx) = l;
                idx = (size_t)(row + 8) * ldc + col;
                split2(acc[mi][nj][2], acc[mi][nj][3], h, l);
                *reinterpret_cast<uint32_t*>(Chi + idx) = h;
                *reinterpret_cast<uint32_t*>(Clo + idx) = l;
            }
    } else if (MODE == 2) {
        __syncthreads();                                 // reuse ring smem
        float* red = reinterpret_cast<float*>(dsm);      // 128 rows x 4 n-warps
        const int nwid = wid >> 1;
#pragma unroll
        for (int mi = 0; mi < 4; ++mi) {
#pragma unroll
            for (int rp = 0; rp < 2; ++rp) {
                const int lrow = m0 + mi * 16 + tr + rp * 8;
                const int row  = i0 + lrow;
                float part = 0.f;
#pragma unroll
                for (int nj = 0; nj < 8; ++nj) {
                    int col = j0 + n0 + nj * 8 + tc;
                    float e0 = (col     <= row) ? __expf(acc[mi][nj][rp * 2]     * SM_SCALE) : 0.f;
                    float e1 = (col + 1 <= row) ? __expf(acc[mi][nj][rp * 2 + 1] * SM_SCALE) : 0.f;
                    uint32_t h, l;
                    split2(e0, e1, h, l);
                    size_t idx = (size_t)row * ldc + col;
                    *reinterpret_cast<uint32_t*>(Chi + idx) = h;
                    *reinterpret_cast<uint32_t*>(Clo + idx) = l;
                    part += e0 + e1;
                }
                part += __shfl_xor_sync(0xffffffffu, part, 1);
                part += __shfl_xor_sync(0xffffffffu, part, 2);
                if ((lane & 3) == 0) red[lrow * 4 + nwid] = part;
            }
        }
        __syncthreads();
        if (tid < 128) {
            float s = red[tid * 4] + red[tid * 4 + 1] + red[tid * 4 + 2] + red[tid * 4 + 3];
            g_partial[(size_t)(rs_off + i0 + tid) * 16 + (j0 >> 8)] = s;
        }
    } else {  // MODE 3: pv, normalize by row sums
#pragma unroll
        for (int mi = 0; mi < 4; ++mi) {
            int row = i0 + m0 + mi * 16 + tr;
            float s0 = 1.0f / g_rowsum[rs_off + row];
            float s1 = 1.0f / g_rowsum[rs_off + row + 8];
#pragma unroll
            for (int nj = 0; nj < 8; ++nj) {
                int col = j0 + n0 + nj * 8 + tc;
                *reinterpret_cast<float2*>(C + (size_t)row * ldc + col) =
                    make_float2(acc[mi][nj][0] * s0, acc[mi][nj][1] * s0);
                *reinterpret_cast<float2*>(C + (size_t)(row + 8) * ldc + col) =
                    make_float2(acc[mi][nj][2] * s1, acc[mi][nj][3] * s1);
            }
        }
    }
}

// ---------------- GEMM stage kernels ------------------------------------------
__global__ void __launch_bounds__(256, 1)
proj_tc()
{
    const int z = blockIdx.z;
    const __nv_bfloat16* Bh = g_WThi + (size_t)z * DIM * DIM;
    const __nv_bfloat16* Bl = g_WTlo + (size_t)z * DIM * DIM;
    __nv_bfloat16* Ch = (z == 0) ? g_Qhi : (z == 1) ? g_Khi : g_Vhi;
    __nv_bfloat16* Cl = (z == 0) ? g_Qlo : (z == 1) ? g_Klo : g_Vlo;
    gemm_pipe<1>(g_Xhi, g_Xlo, DIM, Bh, Bl, DIM,
                 nullptr, Ch, Cl, DIM, blockIdx.y * 128, blockIdx.x * 256, DIM, 0);
}

__global__ void __launch_bounds__(256, 1)
scores_tc()
{
    const int i0 = blockIdx.y * 128, j0 = blockIdx.x * 256;
    if (j0 > i0 + 127) return;   // tile fully above causal diagonal
    const size_t off = (size_t)blockIdx.z * SEQ * DIM;
    __nv_bfloat16* Ch = g_Phi + (size_t)blockIdx.z * SEQ * SEQ;
    __nv_bfloat16* Cl = g_Plo + (size_t)blockIdx.z * SEQ * SEQ;
    gemm_pipe<2>(g_Qhi + off, g_Qlo + off, DIM, g_Khi + off, g_Klo + off, DIM,
                 nullptr, Ch, Cl, SEQ, i0, j0, DIM, blockIdx.z * SEQ);
}

__global__ void __launch_bounds__(256, 1)
pv_tc(float* __restrict__ out)
{
    const int i0 = blockIdx.y * 128, j0 = blockIdx.x * 256;
    const size_t poff = (size_t)blockIdx.z * SEQ * SEQ;
    const size_t voff = (size_t)blockIdx.z * DIM * SEQ;
    float* C = out + (size_t)blockIdx.z * SEQ * DIM;
    gemm_pipe<3>(g_Phi + poff, g_Plo + poff, SEQ, g_VThi + voff, g_VTlo + voff, SEQ,
                 C, nullptr, nullptr, DIM, i0, j0, i0 + 128, blockIdx.z * SEQ);
}

// ---------------- rowsum reduce (deterministic) ---------------------------------
__global__ void __launch_bounds__(256)
reduce_rowsum()
{
    const int i = blockIdx.x * 256 + threadIdx.x;   // global token row
    const int q = i & (SEQ - 1);
    const int nt = (q >> 8) + 1;                    // valid 256-wide tiles
    const float* p = g_partial + (size_t)i * 16;
    float s = 0.f;
    for (int t = 0; t < nt; ++t) s += p[t];
    g_rowsum[i] = s;
}

// ---------------- conversion / transpose kernels -------------------------------
__global__ void conv_x(const float* __restrict__ X)
{
    size_t i = (size_t)blockIdx.x * blockDim.x + threadIdx.x;
    const size_t n4 = (size_t)NTOK * DIM / 4;
    for (; i < n4; i += (size_t)gridDim.x * blockDim.x) {
        float4 v = reinterpret_cast<const float4*>(X)[i];
        uint32_t h0, l0, h1, l1;
        split2(v.x, v.y, h0, l0);
        split2(v.z, v.w, h1, l1);
        reinterpret_cast<uint2*>(g_Xhi)[i] = make_uint2(h0, h1);
        reinterpret_cast<uint2*>(g_Xlo)[i] = make_uint2(l0, l1);
    }
}

__global__ void transpose_w(const float* __restrict__ Wq,
                            const float* __restrict__ Wk,
                            const float* __restrict__ Wv)
{
    const float* src = (blockIdx.z == 0) ? Wq : (blockIdx.z == 1) ? Wk : Wv;
    __nv_bfloat16* dh = g_WThi + (size_t)blockIdx.z * DIM * DIM;
    __nv_bfloat16* dl = g_WTlo + (size_t)blockIdx.z * DIM * DIM;
    __shared__ float t[32][33];
    const int bx = blockIdx.x * 32, by = blockIdx.y * 32;
    const int tx = threadIdx.x, ty = threadIdx.y;
#pragma unroll
    for (int j = 0; j < 32; j += 8)
        t[ty + j][tx] = src[(size_t)(by + ty + j) * DIM + bx + tx];
    __syncthreads();
#pragma unroll
    for (int j = 0; j < 32; j += 8) {
        float v = t[tx][ty + j];
        __nv_bfloat16 h = __float2bfloat16(v);
        size_t idx = (size_t)(bx + ty + j) * DIM + by + tx;
        dh[idx] = h;
        dl[idx] = __float2bfloat16(v - __bfloat162float(h));
    }
}

__global__ void transpose_v()
{
    const int b = blockIdx.z;
    const __nv_bfloat16* sh = g_Vhi + (size_t)b * SEQ * DIM;
    const __nv_bfloat16* sl = g_Vlo + (size_t)b * SEQ * DIM;
    __nv_bfloat16* dh = g_VThi + (size_t)b * DIM * SEQ;
    __nv_bfloat16* dl = g_VTlo + (size_t)b * DIM * SEQ;
    __shared__ float t[32][33];
    const int bx = blockIdx.x * 32, by = blockIdx.y * 32;   // bx over DIM, by over SEQ
    const int tx = threadIdx.x, ty = threadIdx.y;
#pragma unroll
    for (int j = 0; j < 32; j += 8) {
        size_t idx = (size_t)(by + ty + j) * DIM + bx + tx;
        t[ty + j][tx] = __bfloat162float(sh[idx]) + __bfloat162float(sl[idx]);
    }
    __syncthreads();
#pragma unroll
    for (int j = 0; j < 32; j += 8) {
        float v = t[tx][ty + j];
        __nv_bfloat16 h = __float2bfloat16(v);
        size_t idx = (size_t)(bx + ty + j) * SEQ + by + tx;
        dh[idx] = h;
        dl[idx] = __float2bfloat16(v - __bfloat162float(h));
    }
}

// ---------------- launch ---------------------------------------------------------
extern "C" void kernel_launch(void* const* d_in, const int* in_sizes, int n_in,
                              void* d_out, int out_size)
{
    const float* x  = (const float*)d_in[0];
    const float* Wq = (const float*)d_in[1];
    const float* Wk = (const float*)d_in[2];
    const float* Wv = (const float*)d_in[3];
    float* out = (float*)d_out;

    cudaFuncSetAttribute(proj_tc,   cudaFuncAttributeMaxDynamicSharedMemorySize, SMEM_BYTES);
    cudaFuncSetAttribute(scores_tc, cudaFuncAttributeMaxDynamicSharedMemorySize, SMEM_BYTES);
    cudaFuncSetAttribute(pv_tc,     cudaFuncAttributeMaxDynamicSharedMemorySize, SMEM_BYTES);

    dim3 t32(32, 8);
    conv_x<<<512, 256>>>(x);
    transpose_w<<<dim3(DIM / 32, DIM / 32, 3), t32>>>(Wq, Wk, Wv);
    proj_tc<<<dim3(DIM / 256, NTOK / 128, 3), 256, SMEM_BYTES>>>();
    transpose_v<<<dim3(DIM / 32, SEQ / 32, BATCH), t32>>>();
    scores_tc<<<dim3(SEQ / 256, SEQ / 128, BATCH), 256, SMEM_BYTES>>>();
    reduce_rowsum<<<NTOK / 256, 256>>>();
    pv_tc<<<dim3(DIM / 256, SEQ / 128, BATCH), 256, SMEM_BYTES>>>(out);
}

// round 8
// speedup vs baseline: 1.0988x; 1.0988x over previous
#include <cuda_runtime.h>
#include <cuda_bf16.h>
#include <cstdint>

#define BATCH 4
#define SEQ   4096
#define DIM   768
#define NTOK  (BATCH*SEQ)

// ---------------- scratch (__device__ globals: allocation-free rule) --------
__device__ __nv_bfloat16 g_Xhi [(size_t)NTOK * DIM];
__device__ __nv_bfloat16 g_Xlo [(size_t)NTOK * DIM];
__device__ __nv_bfloat16 g_WThi[3ull * DIM * DIM];
__device__ __nv_bfloat16 g_WTlo[3ull * DIM * DIM];
__device__ __nv_bfloat16 g_Qhi [(size_t)NTOK * DIM];
__device__ __nv_bfloat16 g_Qlo [(size_t)NTOK * DIM];
__device__ __nv_bfloat16 g_Khi [(size_t)NTOK * DIM];
__device__ __nv_bfloat16 g_Klo [(size_t)NTOK * DIM];
__device__ __nv_bfloat16 g_Vhi [(size_t)NTOK * DIM];
__device__ __nv_bfloat16 g_Vlo [(size_t)NTOK * DIM];
__device__ __nv_bfloat16 g_VThi[(size_t)BATCH * DIM * SEQ];
__device__ __nv_bfloat16 g_VTlo[(size_t)BATCH * DIM * SEQ];
__device__ __nv_bfloat16 g_Phi [(size_t)BATCH * SEQ * SEQ];   // exp(scores) hi
__device__ __nv_bfloat16 g_Plo [(size_t)BATCH * SEQ * SEQ];   // exp(scores) lo
__device__ float g_partial[(size_t)NTOK * 32];                // per-(row,tile) exp sums
__device__ float g_rowsum [(size_t)NTOK];                     // final row sums

// ---------------- PTX helpers (arch-agnostic, sm_80-class) ------------------
__device__ __forceinline__ uint32_t smem_u32(const void* p) {
    uint32_t a;
    asm("{ .reg .u64 t; cvta.to.shared.u64 t, %1; cvt.u32.u64 %0, t; }"
        : "=r"(a) : "l"(p));
    return a;
}
__device__ __forceinline__ void cp16(uint32_t dst, const void* src) {
    asm volatile("cp.async.cg.shared.global [%0], [%1], 16;"
                 :: "r"(dst), "l"(src) : "memory");
}
#define CP_COMMIT() asm volatile("cp.async.commit_group;" ::: "memory")
#define CP_WAIT(N)  asm volatile("cp.async.wait_group %0;" :: "n"(N) : "memory")

__device__ __forceinline__ void ldsm_x4(uint32_t* r, uint32_t addr) {
    asm volatile("ldmatrix.sync.aligned.m8n8.x4.shared.b16 {%0,%1,%2,%3}, [%4];"
                 : "=r"(r[0]), "=r"(r[1]), "=r"(r[2]), "=r"(r[3]) : "r"(addr));
}
__device__ __forceinline__ void mma16816(float* d, const uint32_t* a, const uint32_t* b) {
    asm volatile(
        "mma.sync.aligned.m16n8k16.row.col.f32.bf16.bf16.f32 "
        "{%0,%1,%2,%3}, {%4,%5,%6,%7}, {%8,%9}, {%0,%1,%2,%3};"
        : "+f"(d[0]), "+f"(d[1]), "+f"(d[2]), "+f"(d[3])
        : "r"(a[0]), "r"(a[1]), "r"(a[2]), "r"(a[3]), "r"(b[0]), "r"(b[1]));
}

// fp32 pair -> bf16 hi pair + bf16 lo pair (packed u32 each)
__device__ __forceinline__ void split2(float a, float b, uint32_t& h, uint32_t& l) {
    __nv_bfloat162 hv = __float22bfloat162_rn(make_float2(a, b));
    float2 f = __bfloat1622float2(hv);
    __nv_bfloat162 lv = __float22bfloat162_rn(make_float2(a - f.x, b - f.y));
    h = *reinterpret_cast<uint32_t*>(&hv);
    l = *reinterpret_cast<uint32_t*>(&lv);
}

// ---------------- pipelined GEMM core ----------------------------------------
// C[128,128] = A[128,K](hi+lo) * B[128,K](hi+lo)^T, bf16 MMA x3, fp32 accum.
// 256 threads, warp grid 2(m) x 4(n), warp tile 64x32, k-step 32, 2-stage cp.async.
// Register-lean: mi chunked by 2 so only half the A fragments are live.
#define LDSE 40                      // smem row stride in bf16 elems (80 B)
#define BUFB (128 * LDSE * 2)        // 10240 B per buffer
#define SMEM_BYTES (2 * 4 * BUFB)    // 81920 B

#define SM_SCALE 0.03608439182435161f   // 1/sqrt(768)

// MODE 1: write split bf16 Chi/Clo (proj).
// MODE 2: exp + causal mask + per-row partial sums -> g_partial; split bf16 out (scores).
// MODE 3: write fp32 C scaled by 1/g_rowsum[row] (pv).
template <int MODE>
__device__ __forceinline__ void gemm_pipe(
    const __nv_bfloat16* __restrict__ Ahi, const __nv_bfloat16* __restrict__ Alo, int lda,
    const __nv_bfloat16* __restrict__ Bhi, const __nv_bfloat16* __restrict__ Blo, int ldb,
    float* __restrict__ C, __nv_bfloat16* __restrict__ Chi, __nv_bfloat16* __restrict__ Clo,
    int ldc, int i0, int j0, int K, int rs_off)
{
    extern __shared__ __align__(16) uint16_t dsm[];
    const uint32_t sb = smem_u32(dsm);

    const int tid  = threadIdx.x;
    const int wid  = tid >> 5;
    const int lane = tid & 31;
    const int m0 = (wid & 1) * 64;
    const int n0 = (wid >> 1) * 32;

    const int a_row = lane & 15;
    const int a_col = (lane >> 4) * 8;
    const int b_row = ((lane >> 4) & 1) * 8 + (lane & 7);
    const int b_col = ((lane >> 3) & 1) * 8;

    const int r0 = tid >> 2,         c0 = (tid & 3) * 8;
    const int r1 = (tid + 256) >> 2, c1 = ((tid + 256) & 3) * 8;

    const __nv_bfloat16* gsrc[4] = {Ahi, Alo, Bhi, Blo};
    const int glda[4] = {lda, lda, ldb, ldb};
    const int grow[4] = {i0, i0, j0, j0};

    const int nk = K >> 5;

    auto stage = [&](int s, int kt) {
#pragma unroll
        for (int b = 0; b < 4; ++b) {
            uint32_t base = sb + (uint32_t)((s * 4 + b) * BUFB);
            const __nv_bfloat16* g = gsrc[b];
            cp16(base + (uint32_t)(r0 * LDSE + c0) * 2,
                 g + (size_t)(grow[b] + r0) * glda[b] + kt + c0);
            cp16(base + (uint32_t)(r1 * LDSE + c1) * 2,
                 g + (size_t)(grow[b] + r1) * glda[b] + kt + c1);
        }
        CP_COMMIT();
    };

    float acc[4][4][4] = {};

    stage(0, 0);
    for (int it = 0; it < nk; ++it) {
        const int s = it & 1;
        if (it + 1 < nk) {
            stage(s ^ 1, (it + 1) << 5);
            CP_WAIT(1);
        } else {
            CP_WAIT(0);
        }
        __syncthreads();

        const uint32_t bAhi = sb + (uint32_t)((s * 4 + 0) * BUFB);
        const uint32_t bAlo = sb + (uint32_t)((s * 4 + 1) * BUFB);
        const uint32_t bBhi = sb + (uint32_t)((s * 4 + 2) * BUFB);
        const uint32_t bBlo = sb + (uint32_t)((s * 4 + 3) * BUFB);

#pragma unroll
        for (int kk = 0; kk < 32; kk += 16) {
#pragma unroll
            for (int mc = 0; mc < 4; mc += 2) {       // mi chunk of 2: A frags lean
                uint32_t aH[2][4], aL[2][4];
#pragma unroll
                for (int mi = 0; mi < 2; ++mi) {
                    uint32_t off = (uint32_t)((m0 + (mc + mi) * 16 + a_row) * LDSE
                                              + kk + a_col) * 2;
                    ldsm_x4(aH[mi], bAhi + off);
                    ldsm_x4(aL[mi], bAlo + off);
                }
#pragma unroll
                for (int nj = 0; nj < 2; ++nj) {
                    uint32_t off = (uint32_t)((n0 + nj * 16 + b_row) * LDSE
                                              + kk + b_col) * 2;
                    uint32_t bh[4], bl[4];
                    ldsm_x4(bh, bBhi + off);
                    ldsm_x4(bl, bBlo + off);
#pragma unroll
                    for (int mi = 0; mi < 2; ++mi) {
                        float* a0 = acc[mc + mi][nj * 2];
                        float* a1 = acc[mc + mi][nj * 2 + 1];
                        mma16816(a0, aH[mi], bh);
                        mma16816(a1, aH[mi], bh + 2);
                        mma16816(a0, aH[mi], bl);
                        mma16816(a1, aH[mi], bl + 2);
                        mma16816(a0, aL[mi], bh);
                        mma16816(a1, aL[mi], bh + 2);
                    }
                }
            }
        }
        __syncthreads();
    }

    // ---- epilogue ------------------------------------------------------------
    const int tr = lane >> 2;
    const int tc = (lane & 3) * 2;

    if (MODE == 1) {
#pragma unroll
        for (int mi = 0; mi < 4; ++mi)
#pragma unroll
            for (int nj = 0; nj < 4; ++nj) {
                int row = i0 + m0 + mi * 16 + tr;
                int col = j0 + n0 + nj * 8 + tc;
                uint32_t h, l;
                size_t idx = (size_t)row * ldc + col;
                split2(acc[mi][nj][0], acc[mi][nj][1], h, l);
                *reinterpret_cast<uint32_t*>(Chi + idx) = h;
                *reinterpret_cast<uint32_t*>(Clo + idx) = l;
                idx = (size_t)(row + 8) * ldc + col;
                split2(acc[mi][nj][2], acc[mi][nj][3], h, l);
                *reinterpret_cast<uint32_t*>(Chi + idx) = h;
                *reinterpret_cast<uint32_t*>(Clo + idx) = l;
            }
    } else if (MODE == 2) {
        // exp + causal mask + row partial sums (deterministic, no atomics)
        float* red = reinterpret_cast<float*>(dsm);     // 128 rows x 4 n-warps
        const int nwid = wid >> 1;
#pragma unroll
        for (int mi = 0; mi < 4; ++mi) {
#pragma unroll
            for (int rp = 0; rp < 2; ++rp) {
                const int lrow = m0 + mi * 16 + tr + rp * 8;
                const int row  = i0 + lrow;
                float part = 0.f;
#pragma unroll
                for (int nj = 0; nj < 4; ++nj) {
                    int col = j0 + n0 + nj * 8 + tc;
                    float e0 = (col     <= row) ? __expf(acc[mi][nj][rp * 2]     * SM_SCALE) : 0.f;
                    float e1 = (col + 1 <= row) ? __expf(acc[mi][nj][rp * 2 + 1] * SM_SCALE) : 0.f;
                    uint32_t h, l;
                    split2(e0, e1, h, l);
                    size_t idx = (size_t)row * ldc + col;
                    *reinterpret_cast<uint32_t*>(Chi + idx) = h;
                    *reinterpret_cast<uint32_t*>(Clo + idx) = l;
                    part += e0 + e1;
                }
                part += __shfl_xor_sync(0xffffffffu, part, 1);
                part += __shfl_xor_sync(0xffffffffu, part, 2);
                if ((lane & 3) == 0) red[lrow * 4 + nwid] = part;
            }
        }
        __syncthreads();
        if (tid < 128) {
            float s = red[tid * 4] + red[tid * 4 + 1] + red[tid * 4 + 2] + red[tid * 4 + 3];
            g_partial[(size_t)(rs_off + i0 + tid) * 32 + (j0 >> 7)] = s;
        }
    } else {  // MODE 3: pv, normalize by row sums
#pragma unroll
        for (int mi = 0; mi < 4; ++mi) {
            int row = i0 + m0 + mi * 16 + tr;
            float s0 = 1.0f / g_rowsum[rs_off + row];
            float s1 = 1.0f / g_rowsum[rs_off + row + 8];
#pragma unroll
            for (int nj = 0; nj < 4; ++nj) {
                int col = j0 + n0 + nj * 8 + tc;
                *reinterpret_cast<float2*>(C + (size_t)row * ldc + col) =
                    make_float2(acc[mi][nj][0] * s0, acc[mi][nj][1] * s0);
                *reinterpret_cast<float2*>(C + (size_t)(row + 8) * ldc + col) =
                    make_float2(acc[mi][nj][2] * s1, acc[mi][nj][3] * s1);
            }
        }
    }
}

// ---------------- GEMM stage kernels ------------------------------------------
__global__ void __launch_bounds__(256, 2)
proj_tc()
{
    const int z = blockIdx.z;
    const __nv_bfloat16* Bh = g_WThi + (size_t)z * DIM * DIM;
    const __nv_bfloat16* Bl = g_WTlo + (size_t)z * DIM * DIM;
    __nv_bfloat16* Ch = (z == 0) ? g_Qhi : (z == 1) ? g_Khi : g_Vhi;
    __nv_bfloat16* Cl = (z == 0) ? g_Qlo : (z == 1) ? g_Klo : g_Vlo;
    gemm_pipe<1>(g_Xhi, g_Xlo, DIM, Bh, Bl, DIM,
                 nullptr, Ch, Cl, DIM, blockIdx.y * 128, blockIdx.x * 128, DIM, 0);
}

__global__ void __launch_bounds__(256, 2)
scores_tc()
{
    const int i0 = blockIdx.y * 128, j0 = blockIdx.x * 128;
    if (j0 > i0) return;   // fully-masked causal tile
    const size_t off = (size_t)blockIdx.z * SEQ * DIM;
    __nv_bfloat16* Ch = g_Phi + (size_t)blockIdx.z * SEQ * SEQ;
    __nv_bfloat16* Cl = g_Plo + (size_t)blockIdx.z * SEQ * SEQ;
    gemm_pipe<2>(g_Qhi + off, g_Qlo + off, DIM, g_Khi + off, g_Klo + off, DIM,
                 nullptr, Ch, Cl, SEQ, i0, j0, DIM, blockIdx.z * SEQ);
}

__global__ void __launch_bounds__(256, 2)
pv_tc(float* __restrict__ out)
{
    const int i0 = blockIdx.y * 128, j0 = blockIdx.x * 128;
    const size_t poff = (size_t)blockIdx.z * SEQ * SEQ;
    const size_t voff = (size_t)blockIdx.z * DIM * SEQ;
    float* C = out + (size_t)blockIdx.z * SEQ * DIM;
    gemm_pipe<3>(g_Phi + poff, g_Plo + poff, SEQ, g_VThi + voff, g_VTlo + voff, SEQ,
                 C, nullptr, nullptr, DIM, i0, j0, i0 + 128, blockIdx.z * SEQ);
}

// ---------------- rowsum reduce (deterministic) ---------------------------------
__global__ void __launch_bounds__(256)
reduce_rowsum()
{
    const int i = blockIdx.x * 256 + threadIdx.x;   // global token row
    const int q = i & (SEQ - 1);
    const int nt = (q >> 7) + 1;                    // valid tiles for this row
    const float* p = g_partial + (size_t)i * 32;
    float s = 0.f;
    for (int t = 0; t < nt; ++t) s += p[t];
    g_rowsum[i] = s;
}

// ---------------- conversion / transpose kernels -------------------------------
__global__ void conv_x(const float* __restrict__ X)
{
    size_t i = (size_t)blockIdx.x * blockDim.x + threadIdx.x;
    const size_t n4 = (size_t)NTOK * DIM / 4;
    for (; i < n4; i += (size_t)gridDim.x * blockDim.x) {
        float4 v = reinterpret_cast<const float4*>(X)[i];
        uint32_t h0, l0, h1, l1;
        split2(v.x, v.y, h0, l0);
        split2(v.z, v.w, h1, l1);
        reinterpret_cast<uint2*>(g_Xhi)[i] = make_uint2(h0, h1);
        reinterpret_cast<uint2*>(g_Xlo)[i] = make_uint2(l0, l1);
    }
}

__global__ void transpose_w(const float* __restrict__ Wq,
                            const float* __restrict__ Wk,
                            const float* __restrict__ Wv)
{
    const float* src = (blockIdx.z == 0) ? Wq : (blockIdx.z == 1) ? Wk : Wv;
    __nv_bfloat16* dh = g_WThi + (size_t)blockIdx.z * DIM * DIM;
    __nv_bfloat16* dl = g_WTlo + (size_t)blockIdx.z * DIM * DIM;
    __shared__ float t[32][33];
    const int bx = blockIdx.x * 32, by = blockIdx.y * 32;
    const int tx = threadIdx.x, ty = threadIdx.y;
#pragma unroll
    for (int j = 0; j < 32; j += 8)
        t[ty + j][tx] = src[(size_t)(by + ty + j) * DIM + bx + tx];
    __syncthreads();
#pragma unroll
    for (int j = 0; j < 32; j += 8) {
        float v = t[tx][ty + j];
        __nv_bfloat16 h = __float2bfloat16(v);
        size_t idx = (size_t)(bx + ty + j) * DIM + by + tx;
        dh[idx] = h;
        dl[idx] = __float2bfloat16(v - __bfloat162float(h));
    }
}

__global__ void transpose_v()
{
    const int b = blockIdx.z;
    const __nv_bfloat16* sh = g_Vhi + (size_t)b * SEQ * DIM;
    const __nv_bfloat16* sl = g_Vlo + (size_t)b * SEQ * DIM;
    __nv_bfloat16* dh = g_VThi + (size_t)b * DIM * SEQ;
    __nv_bfloat16* dl = g_VTlo + (size_t)b * DIM * SEQ;
    __shared__ float t[32][33];
    const int bx = blockIdx.x * 32, by = blockIdx.y * 32;   // bx over DIM, by over SEQ
    const int tx = threadIdx.x, ty = threadIdx.y;
#pragma unroll
    for (int j = 0; j < 32; j += 8) {
        size_t idx = (size_t)(by + ty + j) * DIM + bx + tx;
        t[ty + j][tx] = __bfloat162float(sh[idx]) + __bfloat162float(sl[idx]);
    }
    __syncthreads();
#pragma unroll
    for (int j = 0; j < 32; j += 8) {
        float v = t[tx][ty + j];
        __nv_bfloat16 h = __float2bfloat16(v);
        size_t idx = (size_t)(bx + ty + j) * SEQ + by + tx;
        dh[idx] = h;
        dl[idx] = __float2bfloat16(v - __bfloat162float(h));
    }
}

// ---------------- launch ---------------------------------------------------------
extern "C" void kernel_launch(void* const* d_in, const int* in_sizes, int n_in,
                              void* d_out, int out_size)
{
    const float* x  = (const float*)d_in[0];
    const float* Wq = (const float*)d_in[1];
    const float* Wk = (const float*)d_in[2];
    const float* Wv = (const float*)d_in[3];
    float* out = (float*)d_out;

    cudaFuncSetAttribute(proj_tc,   cudaFuncAttributeMaxDynamicSharedMemorySize, SMEM_BYTES);
    cudaFuncSetAttribute(scores_tc, cudaFuncAttributeMaxDynamicSharedMemorySize, SMEM_BYTES);
    cudaFuncSetAttribute(pv_tc,     cudaFuncAttributeMaxDynamicSharedMemorySize, SMEM_BYTES);

    dim3 t32(32, 8);
    conv_x<<<512, 256>>>(x);
    transpose_w<<<dim3(DIM / 32, DIM / 32, 3), t32>>>(Wq, Wk, Wv);
    proj_tc<<<dim3(DIM / 128, NTOK / 128, 3), 256, SMEM_BYTES>>>();
    transpose_v<<<dim3(DIM / 32, SEQ / 32, BATCH), t32>>>();
    scores_tc<<<dim3(SEQ / 128, SEQ / 128, BATCH), 256, SMEM_BYTES>>>();
    reduce_rowsum<<<NTOK / 256, 256>>>();
    pv_tc<<<dim3(DIM / 128, SEQ / 128, BATCH), 256, SMEM_BYTES>>>(out);
}

// round 9
// speedup vs baseline: 1.4920x; 1.3579x over previous
#include <cuda_runtime.h>
#include <cuda_fp16.h>
#include <cstdint>

#define BATCH 4
#define SEQ   4096
#define DIM   768
#define NTOK  (BATCH*SEQ)

// ---------------- scratch (__device__ globals: allocation-free rule) --------
// A-side operands keep an exact fp16 hi+lo split; B-side operands are fp16 (hi only).
__device__ __half g_Xhi [(size_t)NTOK * DIM];
__device__ __half g_Xlo [(size_t)NTOK * DIM];
__device__ __half g_WThi[3ull * DIM * DIM];               // B side: hi only
__device__ __half g_Qhi [(size_t)NTOK * DIM];
__device__ __half g_Qlo [(size_t)NTOK * DIM];
__device__ __half g_Khi [(size_t)NTOK * DIM];             // B side in scores
__device__ __half g_Klo [(size_t)NTOK * DIM];             // (written, unused)
__device__ __half g_Vhi [(size_t)NTOK * DIM];
__device__ __half g_Vlo [(size_t)NTOK * DIM];
__device__ __half g_VThi[(size_t)BATCH * DIM * SEQ];      // B side: hi only
__device__ __half g_Phi [(size_t)BATCH * SEQ * SEQ];      // exp(scores)/64 hi
__device__ __half g_Plo [(size_t)BATCH * SEQ * SEQ];      // exp(scores)/64 lo
__device__ float g_partial[(size_t)NTOK * 32];            // per-(row,tile) sums
__device__ float g_rowsum [(size_t)NTOK];                 // final row sums

// ---------------- PTX helpers (arch-agnostic, sm_80-class) ------------------
__device__ __forceinline__ uint32_t smem_u32(const void* p) {
    uint32_t a;
    asm("{ .reg .u64 t; cvta.to.shared.u64 t, %1; cvt.u32.u64 %0, t; }"
        : "=r"(a) : "l"(p));
    return a;
}
__device__ __forceinline__ void cp16(uint32_t dst, const void* src) {
    asm volatile("cp.async.cg.shared.global [%0], [%1], 16;"
                 :: "r"(dst), "l"(src) : "memory");
}
#define CP_COMMIT() asm volatile("cp.async.commit_group;" ::: "memory")
#define CP_WAIT(N)  asm volatile("cp.async.wait_group %0;" :: "n"(N) : "memory")

__device__ __forceinline__ void ldsm_x4(uint32_t* r, uint32_t addr) {
    asm volatile("ldmatrix.sync.aligned.m8n8.x4.shared.b16 {%0,%1,%2,%3}, [%4];"
                 : "=r"(r[0]), "=r"(r[1]), "=r"(r[2]), "=r"(r[3]) : "r"(addr));
}
__device__ __forceinline__ void mma16816(float* d, const uint32_t* a, const uint32_t* b) {
    asm volatile(
        "mma.sync.aligned.m16n8k16.row.col.f32.f16.f16.f32 "
        "{%0,%1,%2,%3}, {%4,%5,%6,%7}, {%8,%9}, {%0,%1,%2,%3};"
        : "+f"(d[0]), "+f"(d[1]), "+f"(d[2]), "+f"(d[3])
        : "r"(a[0]), "r"(a[1]), "r"(a[2]), "r"(a[3]), "r"(b[0]), "r"(b[1]));
}

// fp32 pair -> fp16 hi pair + fp16 lo pair (packed u32 each); hi+lo = x to ~2^-22
__device__ __forceinline__ void split2h(float a, float b, uint32_t& h, uint32_t& l) {
    __half2 hv = __floats2half2_rn(a, b);
    float2 f = __half22float2(hv);
    __half2 lv = __floats2half2_rn(a - f.x, b - f.y);
    h = *reinterpret_cast<uint32_t*>(&hv);
    l = *reinterpret_cast<uint32_t*>(&lv);
}
__device__ __forceinline__ __half h_hi(float v) { return __float2half_rn(v); }
__device__ __forceinline__ __half h_lo(float v, __half h) {
    return __float2half_rn(v - __half2float(h));
}

// ---------------- pipelined GEMM core ----------------------------------------
// C[128,128] = (Ahi+Alo)[128,K] * Bhi[128,K]^T, fp16 MMA x2, fp32 accum.
// 256 threads, warp grid 2(m) x 4(n), warp tile 64x32, k-step 32, 2-stage cp.async.
#define LDSE 40                      // smem row stride (fp16): conflict-free ldsm
#define BUFB (128 * LDSE * 2)        // 10240 B per buffer
#define SMEM_BYTES (2 * 3 * BUFB)    // 61440 B (3 buffers/stage)

#define SM_SCALE 0.03608439182435161f   // 1/sqrt(768)
#define P_SCALE  0.015625f              // store exp/64 (overflow headroom in fp16)

// MODE 1: write split fp16 Chi/Clo (proj).
// MODE 2: exp/64 + causal mask + per-row partial sums -> g_partial; split fp16 out.
// MODE 3: write fp32 C scaled by 1/g_rowsum[row] (pv; rowsum also /64 -> cancels).
template <int MODE>
__device__ __forceinline__ void gemm_pipe(
    const __half* __restrict__ Ahi, const __half* __restrict__ Alo, int lda,
    const __half* __restrict__ Bhi, int ldb,
    float* __restrict__ C, __half* __restrict__ Chi, __half* __restrict__ Clo,
    int ldc, int i0, int j0, int K, int rs_off)
{
    extern __shared__ __align__(16) uint16_t dsm[];
    const uint32_t sb = smem_u32(dsm);

    const int tid  = threadIdx.x;
    const int wid  = tid >> 5;
    const int lane = tid & 31;
    const int m0 = (wid & 1) * 64;
    const int n0 = (wid >> 1) * 32;

    const int a_row = lane & 15;
    const int a_col = (lane >> 4) * 8;
    const int b_row = ((lane >> 4) & 1) * 8 + (lane & 7);
    const int b_col = ((lane >> 3) & 1) * 8;

    const int r0 = tid >> 2,         c0 = (tid & 3) * 8;
    const int r1 = (tid + 256) >> 2, c1 = ((tid + 256) & 3) * 8;

    const __half* gsrc[3] = {Ahi, Alo, Bhi};
    const int glda[3] = {lda, lda, ldb};
    const int grow[3] = {i0, i0, j0};

    const int nk = K >> 5;

    auto stage = [&](int s, int kt) {
#pragma unroll
        for (int b = 0; b < 3; ++b) {
            uint32_t base = sb + (uint32_t)((s * 3 + b) * BUFB);
            const __half* g = gsrc[b];
            cp16(base + (uint32_t)(r0 * LDSE + c0) * 2,
                 g + (size_t)(grow[b] + r0) * glda[b] + kt + c0);
            cp16(base + (uint32_t)(r1 * LDSE + c1) * 2,
                 g + (size_t)(grow[b] + r1) * glda[b] + kt + c1);
        }
        CP_COMMIT();
    };

    float acc[4][4][4] = {};

    stage(0, 0);
    for (int it = 0; it < nk; ++it) {
        const int s = it & 1;
        if (it + 1 < nk) {
            stage(s ^ 1, (it + 1) << 5);
            CP_WAIT(1);
        } else {
            CP_WAIT(0);
        }
        __syncthreads();

        const uint32_t bAhi = sb + (uint32_t)((s * 3 + 0) * BUFB);
        const uint32_t bAlo = sb + (uint32_t)((s * 3 + 1) * BUFB);
        const uint32_t bBhi = sb + (uint32_t)((s * 3 + 2) * BUFB);

#pragma unroll
        for (int kk = 0; kk < 32; kk += 16) {
            uint32_t aH[4][4], aL[4][4];
#pragma unroll
            for (int mi = 0; mi < 4; ++mi) {
                uint32_t off = (uint32_t)((m0 + mi * 16 + a_row) * LDSE + kk + a_col) * 2;
                ldsm_x4(aH[mi], bAhi + off);
                ldsm_x4(aL[mi], bAlo + off);
            }
#pragma unroll
            for (int nj = 0; nj < 2; ++nj) {
                uint32_t off = (uint32_t)((n0 + nj * 16 + b_row) * LDSE + kk + b_col) * 2;
                uint32_t bh[4];
                ldsm_x4(bh, bBhi + off);
#pragma unroll
                for (int mi = 0; mi < 4; ++mi) {
                    float* a0 = acc[mi][nj * 2];
                    float* a1 = acc[mi][nj * 2 + 1];
                    mma16816(a0, aH[mi], bh);        // hi_a * B
                    mma16816(a1, aH[mi], bh + 2);
                    mma16816(a0, aL[mi], bh);        // lo_a * B
                    mma16816(a1, aL[mi], bh + 2);
                }
            }
        }
        __syncthreads();
    }

    // ---- epilogue ------------------------------------------------------------
    const int tr = lane >> 2;
    const int tc = (lane & 3) * 2;

    if (MODE == 1) {
#pragma unroll
        for (int mi = 0; mi < 4; ++mi)
#pragma unroll
            for (int nj = 0; nj < 4; ++nj) {
                int row = i0 + m0 + mi * 16 + tr;
                int col = j0 + n0 + nj * 8 + tc;
                uint32_t h, l;
                size_t idx = (size_t)row * ldc + col;
                split2h(acc[mi][nj][0], acc[mi][nj][1], h, l);
                *reinterpret_cast<uint32_t*>(Chi + idx) = h;
                *reinterpret_cast<uint32_t*>(Clo + idx) = l;
                idx = (size_t)(row + 8) * ldc + col;
                split2h(acc[mi][nj][2], acc[mi][nj][3], h, l);
                *reinterpret_cast<uint32_t*>(Chi + idx) = h;
                *reinterpret_cast<uint32_t*>(Clo + idx) = l;
            }
    } else if (MODE == 2) {
        float* red = reinterpret_cast<float*>(dsm);     // 128 rows x 4 n-warps
        const int nwid = wid >> 1;
#pragma unroll
        for (int mi = 0; mi < 4; ++mi) {
#pragma unroll
            for (int rp = 0; rp < 2; ++rp) {
                const int lrow = m0 + mi * 16 + tr + rp * 8;
                const int row  = i0 + lrow;
                float part = 0.f;
#pragma unroll
                for (int nj = 0; nj < 4; ++nj) {
                    int col = j0 + n0 + nj * 8 + tc;
                    float e0 = (col     <= row)
                        ? __expf(acc[mi][nj][rp * 2]     * SM_SCALE) * P_SCALE : 0.f;
                    float e1 = (col + 1 <= row)
                        ? __expf(acc[mi][nj][rp * 2 + 1] * SM_SCALE) * P_SCALE : 0.f;
                    uint32_t h, l;
                    split2h(e0, e1, h, l);
                    size_t idx = (size_t)row * ldc + col;
                    *reinterpret_cast<uint32_t*>(Chi + idx) = h;
                    *reinterpret_cast<uint32_t*>(Clo + idx) = l;
                    part += e0 + e1;
                }
                part += __shfl_xor_sync(0xffffffffu, part, 1);
                part += __shfl_xor_sync(0xffffffffu, part, 2);
                if ((lane & 3) == 0) red[lrow * 4 + nwid] = part;
            }
        }
        __syncthreads();
        if (tid < 128) {
            float s = red[tid * 4] + red[tid * 4 + 1] + red[tid * 4 + 2] + red[tid * 4 + 3];
            g_partial[(size_t)(rs_off + i0 + tid) * 32 + (j0 >> 7)] = s;
        }
    } else {  // MODE 3: pv, normalize by row sums (both scaled by 1/64 -> cancels)
#pragma unroll
        for (int mi = 0; mi < 4; ++mi) {
            int row = i0 + m0 + mi * 16 + tr;
            float s0 = 1.0f / g_rowsum[rs_off + row];
            float s1 = 1.0f / g_rowsum[rs_off + row + 8];
#pragma unroll
            for (int nj = 0; nj < 4; ++nj) {
                int col = j0 + n0 + nj * 8 + tc;
                *reinterpret_cast<float2*>(C + (size_t)row * ldc + col) =
                    make_float2(acc[mi][nj][0] * s0, acc[mi][nj][1] * s0);
                *reinterpret_cast<float2*>(C + (size_t)(row + 8) * ldc + col) =
                    make_float2(acc[mi][nj][2] * s1, acc[mi][nj][3] * s1);
            }
        }
    }
}

// ---------------- GEMM stage kernels ------------------------------------------
__global__ void __launch_bounds__(256, 2)
proj_tc()
{
    const int z = blockIdx.z;
    const __half* Bh = g_WThi + (size_t)z * DIM * DIM;
    __half* Ch = (z == 0) ? g_Qhi : (z == 1) ? g_Khi : g_Vhi;
    __half* Cl = (z == 0) ? g_Qlo : (z == 1) ? g_Klo : g_Vlo;
    gemm_pipe<1>(g_Xhi, g_Xlo, DIM, Bh, DIM,
                 nullptr, Ch, Cl, DIM, blockIdx.y * 128, blockIdx.x * 128, DIM, 0);
}

__global__ void __launch_bounds__(256, 2)
scores_tc()
{
    const int i0 = blockIdx.y * 128, j0 = blockIdx.x * 128;
    if (j0 > i0) return;   // fully-masked causal tile
    const size_t off = (size_t)blockIdx.z * SEQ * DIM;
    __half* Ch = g_Phi + (size_t)blockIdx.z * SEQ * SEQ;
    __half* Cl = g_Plo + (size_t)blockIdx.z * SEQ * SEQ;
    gemm_pipe<2>(g_Qhi + off, g_Qlo + off, DIM, g_Khi + off, DIM,
                 nullptr, Ch, Cl, SEQ, i0, j0, DIM, blockIdx.z * SEQ);
}

__global__ void __launch_bounds__(256, 2)
pv_tc(float* __restrict__ out)
{
    const int i0 = blockIdx.y * 128, j0 = blockIdx.x * 128;
    const size_t poff = (size_t)blockIdx.z * SEQ * SEQ;
    const size_t voff = (size_t)blockIdx.z * DIM * SEQ;
    float* C = out + (size_t)blockIdx.z * SEQ * DIM;
    gemm_pipe<3>(g_Phi + poff, g_Plo + poff, SEQ, g_VThi + voff, SEQ,
                 C, nullptr, nullptr, DIM, i0, j0, i0 + 128, blockIdx.z * SEQ);
}

// ---------------- rowsum reduce (deterministic) ---------------------------------
__global__ void __launch_bounds__(256)
reduce_rowsum()
{
    const int i = blockIdx.x * 256 + threadIdx.x;   // global token row
    const int q = i & (SEQ - 1);
    const int nt = (q >> 7) + 1;                    // valid tiles for this row
    const float* p = g_partial + (size_t)i * 32;
    float s = 0.f;
    for (int t = 0; t < nt; ++t) s += p[t];
    g_rowsum[i] = s;
}

// ---------------- conversion / transpose kernels -------------------------------
__global__ void conv_x(const float* __restrict__ X)
{
    size_t i = (size_t)blockIdx.x * blockDim.x + threadIdx.x;
    const size_t n4 = (size_t)NTOK * DIM / 4;
    for (; i < n4; i += (size_t)gridDim.x * blockDim.x) {
        float4 v = reinterpret_cast<const float4*>(X)[i];
        uint32_t h0, l0, h1, l1;
        split2h(v.x, v.y, h0, l0);
        split2h(v.z, v.w, h1, l1);
        reinterpret_cast<uint2*>(g_Xhi)[i] = make_uint2(h0, h1);
        reinterpret_cast<uint2*>(g_Xlo)[i] = make_uint2(l0, l1);
    }
}

__global__ void transpose_w(const float* __restrict__ Wq,
                            const float* __restrict__ Wk,
                            const float* __restrict__ Wv)
{
    const float* src = (blockIdx.z == 0) ? Wq : (blockIdx.z == 1) ? Wk : Wv;
    __half* dh = g_WThi + (size_t)blockIdx.z * DIM * DIM;
    __shared__ float t[32][33];
    const int bx = blockIdx.x * 32, by = blockIdx.y * 32;
    const int tx = threadIdx.x, ty = threadIdx.y;
#pragma unroll
    for (int j = 0; j < 32; j += 8)
        t[ty + j][tx] = src[(size_t)(by + ty + j) * DIM + bx + tx];
    __syncthreads();
#pragma unroll
    for (int j = 0; j < 32; j += 8)
        dh[(size_t)(bx + ty + j) * DIM + by + tx] = h_hi(t[tx][ty + j]);
}

__global__ void transpose_v()
{
    const int b = blockIdx.z;
    const __half* sh = g_Vhi + (size_t)b * SEQ * DIM;
    const __half* sl = g_Vlo + (size_t)b * SEQ * DIM;
    __half* dh = g_VThi + (size_t)b * DIM * SEQ;
    __shared__ float t[32][33];
    const int bx = blockIdx.x * 32, by = blockIdx.y * 32;   // bx over DIM, by over SEQ
    const int tx = threadIdx.x, ty = threadIdx.y;
#pragma unroll
    for (int j = 0; j < 32; j += 8) {
        size_t idx = (size_t)(by + ty + j) * DIM + bx + tx;
        t[ty + j][tx] = __half2float(sh[idx]) + __half2float(sl[idx]);
    }
    __syncthreads();
#pragma unroll
    for (int j = 0; j < 32; j += 8)
        dh[(size_t)(bx + ty + j) * SEQ + by + tx] = h_hi(t[tx][ty + j]);
}

// ---------------- launch ---------------------------------------------------------
extern "C" void kernel_launch(void* const* d_in, const int* in_sizes, int n_in,
                              void* d_out, int out_size)
{
    const float* x  = (const float*)d_in[0];
    const float* Wq = (const float*)d_in[1];
    const float* Wk = (const float*)d_in[2];
    const float* Wv = (const float*)d_in[3];
    float* out = (float*)d_out;

    cudaFuncSetAttribute(proj_tc,   cudaFuncAttributeMaxDynamicSharedMemorySize, SMEM_BYTES);
    cudaFuncSetAttribute(scores_tc, cudaFuncAttributeMaxDynamicSharedMemorySize, SMEM_BYTES);
    cudaFuncSetAttribute(pv_tc,     cudaFuncAttributeMaxDynamicSharedMemorySize, SMEM_BYTES);

    dim3 t32(32, 8);
    conv_x<<<512, 256>>>(x);
    transpose_w<<<dim3(DIM / 32, DIM / 32, 3), t32>>>(Wq, Wk, Wv);
    proj_tc<<<dim3(DIM / 128, NTOK / 128, 3), 256, SMEM_BYTES>>>();
    transpose_v<<<dim3(DIM / 32, SEQ / 32, BATCH), t32>>>();
    scores_tc<<<dim3(SEQ / 128, SEQ / 128, BATCH), 256, SMEM_BYTES>>>();
    reduce_rowsum<<<NTOK / 256, 256>>>();
    pv_tc<<<dim3(DIM / 128, SEQ / 128, BATCH), 256, SMEM_BYTES>>>(out);
}

// round 10
// speedup vs baseline: 1.7756x; 1.1901x over previous
#include <cuda_runtime.h>
#include <cuda_fp16.h>
#include <cstdint>

#define BATCH 4
#define SEQ   4096
#define DIM   768
#define NTOK  (BATCH*SEQ)

// ---------------- scratch (__device__ globals: allocation-free rule) --------
// A-side operands keep an exact fp16 hi+lo split; B-side operands are fp16 (hi only).
// P (probs) is fp16 single-term: weights in [0,1]/64, rounding error ~2^-11 RMS-safe.
__device__ __half g_Xhi [(size_t)NTOK * DIM];
__device__ __half g_Xlo [(size_t)NTOK * DIM];
__device__ __half g_WThi[3ull * DIM * DIM];               // B side: hi only
__device__ __half g_Qhi [(size_t)NTOK * DIM];
__device__ __half g_Qlo [(size_t)NTOK * DIM];
__device__ __half g_Khi [(size_t)NTOK * DIM];             // B side in scores
__device__ __half g_Klo [(size_t)NTOK * DIM];             // (written, unused)
__device__ __half g_Vhi [(size_t)NTOK * DIM];
__device__ __half g_Vlo [(size_t)NTOK * DIM];
__device__ __half g_VThi[(size_t)BATCH * DIM * SEQ];      // B side: hi only
__device__ __half g_Phi [(size_t)BATCH * SEQ * SEQ];      // exp(scores)/64, fp16
__device__ float g_partial[(size_t)NTOK * 32];            // per-(row,tile) sums
__device__ float g_rowsum [(size_t)NTOK];                 // final row sums

// ---------------- PTX helpers (arch-agnostic, sm_80-class) ------------------
__device__ __forceinline__ uint32_t smem_u32(const void* p) {
    uint32_t a;
    asm("{ .reg .u64 t; cvta.to.shared.u64 t, %1; cvt.u32.u64 %0, t; }"
        : "=r"(a) : "l"(p));
    return a;
}
__device__ __forceinline__ void cp16(uint32_t dst, const void* src) {
    asm volatile("cp.async.cg.shared.global [%0], [%1], 16;"
                 :: "r"(dst), "l"(src) : "memory");
}
#define CP_COMMIT() asm volatile("cp.async.commit_group;" ::: "memory")
#define CP_WAIT(N)  asm volatile("cp.async.wait_group %0;" :: "n"(N) : "memory")

__device__ __forceinline__ void ldsm_x4(uint32_t* r, uint32_t addr) {
    asm volatile("ldmatrix.sync.aligned.m8n8.x4.shared.b16 {%0,%1,%2,%3}, [%4];"
                 : "=r"(r[0]), "=r"(r[1]), "=r"(r[2]), "=r"(r[3]) : "r"(addr));
}
__device__ __forceinline__ void mma16816(float* d, const uint32_t* a, const uint32_t* b) {
    asm volatile(
        "mma.sync.aligned.m16n8k16.row.col.f32.f16.f16.f32 "
        "{%0,%1,%2,%3}, {%4,%5,%6,%7}, {%8,%9}, {%0,%1,%2,%3};"
        : "+f"(d[0]), "+f"(d[1]), "+f"(d[2]), "+f"(d[3])
        : "r"(a[0]), "r"(a[1]), "r"(a[2]), "r"(a[3]), "r"(b[0]), "r"(b[1]));
}

// fp32 pair -> fp16 hi pair + fp16 lo pair (packed u32 each)
__device__ __forceinline__ void split2h(float a, float b, uint32_t& h, uint32_t& l) {
    __half2 hv = __floats2half2_rn(a, b);
    float2 f = __half22float2(hv);
    __half2 lv = __floats2half2_rn(a - f.x, b - f.y);
    h = *reinterpret_cast<uint32_t*>(&hv);
    l = *reinterpret_cast<uint32_t*>(&lv);
}
__device__ __forceinline__ uint32_t pack2h(float a, float b) {
    __half2 hv = __floats2half2_rn(a, b);
    return *reinterpret_cast<uint32_t*>(&hv);
}
__device__ __forceinline__ __half h_hi(float v) { return __float2half_rn(v); }

// ---------------- pipelined GEMM core ----------------------------------------
// C[128,128] = (Ahi[+Alo])[128,K] * Bhi[128,K]^T, fp16 MMA x NTERMS, fp32 accum.
// 256 threads, warp grid 2(m) x 4(n), warp tile 64x32, k-step 32, 2-stage cp.async.
#define LDSE 40                      // smem row stride (fp16): conflict-free ldsm
#define BUFB (128 * LDSE * 2)        // 10240 B per buffer
#define SMEM_BYTES (2 * 3 * BUFB)    // 61440 B (max: 3 buffers/stage)

#define SM_SCALE 0.03608439182435161f   // 1/sqrt(768)
#define P_SCALE  0.015625f              // store exp/64 (overflow headroom in fp16)

// MODE 1: write split fp16 Chi/Clo (proj).
// MODE 2: exp/64 + causal mask + per-row partial sums -> g_partial; fp16 out (hi only).
// MODE 3: write fp32 C scaled by 1/g_rowsum[row] (pv; rowsum also /64 -> cancels).
// NTERMS: 2 = A hi+lo (3 staged buffers), 1 = A hi only (2 staged buffers).
template <int MODE, int NTERMS>
__device__ __forceinline__ void gemm_pipe(
    const __half* __restrict__ Ahi, const __half* __restrict__ Alo, int lda,
    const __half* __restrict__ Bhi, int ldb,
    float* __restrict__ C, __half* __restrict__ Chi, __half* __restrict__ Clo,
    int ldc, int i0, int j0, int K, int rs_off)
{
    extern __shared__ __align__(16) uint16_t dsm[];
    const uint32_t sb = smem_u32(dsm);

    const int tid  = threadIdx.x;
    const int wid  = tid >> 5;
    const int lane = tid & 31;
    const int m0 = (wid & 1) * 64;
    const int n0 = (wid >> 1) * 32;

    const int a_row = lane & 15;
    const int a_col = (lane >> 4) * 8;
    const int b_row = ((lane >> 4) & 1) * 8 + (lane & 7);
    const int b_col = ((lane >> 3) & 1) * 8;

    const int r0 = tid >> 2,         c0 = (tid & 3) * 8;
    const int r1 = (tid + 256) >> 2, c1 = ((tid + 256) & 3) * 8;

    constexpr int NBUF = NTERMS + 1;                 // A bufs + 1 B buf
    const __half* gsrc[3] = {Ahi, (NTERMS == 2) ? Alo : Bhi, Bhi};
    const int glda[3] = {lda, (NTERMS == 2) ? lda : ldb, ldb};
    const int grow[3] = {i0, (NTERMS == 2) ? i0 : j0, j0};

    const int nk = K >> 5;

    auto stage = [&](int s, int kt) {
#pragma unroll
        for (int b = 0; b < NBUF; ++b) {
            uint32_t base = sb + (uint32_t)((s * NBUF + b) * BUFB);
            const __half* g = gsrc[b];
            cp16(base + (uint32_t)(r0 * LDSE + c0) * 2,
                 g + (size_t)(grow[b] + r0) * glda[b] + kt + c0);
            cp16(base + (uint32_t)(r1 * LDSE + c1) * 2,
                 g + (size_t)(grow[b] + r1) * glda[b] + kt + c1);
        }
        CP_COMMIT();
    };

    float acc[4][4][4] = {};

    stage(0, 0);
    for (int it = 0; it < nk; ++it) {
        const int s = it & 1;
        if (it + 1 < nk) {
            stage(s ^ 1, (it + 1) << 5);
            CP_WAIT(1);
        } else {
            CP_WAIT(0);
        }
        __syncthreads();

        const uint32_t bAhi = sb + (uint32_t)((s * NBUF + 0) * BUFB);
        const uint32_t bAlo = sb + (uint32_t)((s * NBUF + 1) * BUFB);       // NTERMS==2
        const uint32_t bBhi = sb + (uint32_t)((s * NBUF + NBUF - 1) * BUFB);

#pragma unroll
        for (int kk = 0; kk < 32; kk += 16) {
            uint32_t aH[4][4], aL[4][4];
#pragma unroll
            for (int mi = 0; mi < 4; ++mi) {
                uint32_t off = (uint32_t)((m0 + mi * 16 + a_row) * LDSE + kk + a_col) * 2;
                ldsm_x4(aH[mi], bAhi + off);
                if (NTERMS == 2) ldsm_x4(aL[mi], bAlo + off);
            }
#pragma unroll
            for (int nj = 0; nj < 2; ++nj) {
                uint32_t off = (uint32_t)((n0 + nj * 16 + b_row) * LDSE + kk + b_col) * 2;
                uint32_t bh[4];
                ldsm_x4(bh, bBhi + off);
#pragma unroll
                for (int mi = 0; mi < 4; ++mi) {
                    float* a0 = acc[mi][nj * 2];
                    float* a1 = acc[mi][nj * 2 + 1];
                    mma16816(a0, aH[mi], bh);
                    mma16816(a1, aH[mi], bh + 2);
                    if (NTERMS == 2) {
                        mma16816(a0, aL[mi], bh);
                        mma16816(a1, aL[mi], bh + 2);
                    }
                }
            }
        }
        __syncthreads();
    }

    // ---- epilogue ------------------------------------------------------------
    const int tr = lane >> 2;
    const int tc = (lane & 3) * 2;

    if (MODE == 1) {
#pragma unroll
        for (int mi = 0; mi < 4; ++mi)
#pragma unroll
            for (int nj = 0; nj < 4; ++nj) {
                int row = i0 + m0 + mi * 16 + tr;
                int col = j0 + n0 + nj * 8 + tc;
                uint32_t h, l;
                size_t idx = (size_t)row * ldc + col;
                split2h(acc[mi][nj][0], acc[mi][nj][1], h, l);
                *reinterpret_cast<uint32_t*>(Chi + idx) = h;
                *reinterpret_cast<uint32_t*>(Clo + idx) = l;
                idx = (size_t)(row + 8) * ldc + col;
                split2h(acc[mi][nj][2], acc[mi][nj][3], h, l);
                *reinterpret_cast<uint32_t*>(Chi + idx) = h;
                *reinterpret_cast<uint32_t*>(Clo + idx) = l;
            }
    } else if (MODE == 2) {
        float* red = reinterpret_cast<float*>(dsm);     // 128 rows x 4 n-warps
        const int nwid = wid >> 1;
#pragma unroll
        for (int mi = 0; mi < 4; ++mi) {
#pragma unroll
            for (int rp = 0; rp < 2; ++rp) {
                const int lrow = m0 + mi * 16 + tr + rp * 8;
                const int row  = i0 + lrow;
                float part = 0.f;
#pragma unroll
                for (int nj = 0; nj < 4; ++nj) {
                    int col = j0 + n0 + nj * 8 + tc;
                    float e0 = (col     <= row)
                        ? __expf(acc[mi][nj][rp * 2]     * SM_SCALE) * P_SCALE : 0.f;
                    float e1 = (col + 1 <= row)
                        ? __expf(acc[mi][nj][rp * 2 + 1] * SM_SCALE) * P_SCALE : 0.f;
                    size_t idx = (size_t)row * ldc + col;
                    *reinterpret_cast<uint32_t*>(Chi + idx) = pack2h(e0, e1);
                    part += e0 + e1;
                }
                part += __shfl_xor_sync(0xffffffffu, part, 1);
                part += __shfl_xor_sync(0xffffffffu, part, 2);
                if ((lane & 3) == 0) red[lrow * 4 + nwid] = part;
            }
        }
        __syncthreads();
        if (tid < 128) {
            float s = red[tid * 4] + red[tid * 4 + 1] + red[tid * 4 + 2] + red[tid * 4 + 3];
            g_partial[(size_t)(rs_off + i0 + tid) * 32 + (j0 >> 7)] = s;
        }
    } else {  // MODE 3: pv, normalize by row sums (both scaled by 1/64 -> cancels)
#pragma unroll
        for (int mi = 0; mi < 4; ++mi) {
            int row = i0 + m0 + mi * 16 + tr;
            float s0 = 1.0f / g_rowsum[rs_off + row];
            float s1 = 1.0f / g_rowsum[rs_off + row + 8];
#pragma unroll
            for (int nj = 0; nj < 4; ++nj) {
                int col = j0 + n0 + nj * 8 + tc;
                *reinterpret_cast<float2*>(C + (size_t)row * ldc + col) =
                    make_float2(acc[mi][nj][0] * s0, acc[mi][nj][1] * s0);
                *reinterpret_cast<float2*>(C + (size_t)(row + 8) * ldc + col) =
                    make_float2(acc[mi][nj][2] * s1, acc[mi][nj][3] * s1);
            }
        }
    }
}

// ---------------- GEMM stage kernels ------------------------------------------
__global__ void __launch_bounds__(256, 2)
proj_tc()
{
    const int z = blockIdx.z;
    const __half* Bh = g_WThi + (size_t)z * DIM * DIM;
    __half* Ch = (z == 0) ? g_Qhi : (z == 1) ? g_Khi : g_Vhi;
    __half* Cl = (z == 0) ? g_Qlo : (z == 1) ? g_Klo : g_Vlo;
    gemm_pipe<1, 2>(g_Xhi, g_Xlo, DIM, Bh, DIM,
                    nullptr, Ch, Cl, DIM, blockIdx.y * 128, blockIdx.x * 128, DIM, 0);
}

__global__ void __launch_bounds__(256, 2)
scores_tc()
{
    const int i0 = blockIdx.y * 128, j0 = blockIdx.x * 128;
    if (j0 > i0) return;   // fully-masked causal tile
    const size_t off = (size_t)blockIdx.z * SEQ * DIM;
    __half* Ch = g_Phi + (size_t)blockIdx.z * SEQ * SEQ;
    gemm_pipe<2, 2>(g_Qhi + off, g_Qlo + off, DIM, g_Khi + off, DIM,
                    nullptr, Ch, nullptr, SEQ, i0, j0, DIM, blockIdx.z * SEQ);
}

__global__ void __launch_bounds__(256, 2)
pv_tc(float* __restrict__ out)
{
    const int i0 = blockIdx.y * 128, j0 = blockIdx.x * 128;
    const size_t poff = (size_t)blockIdx.z * SEQ * SEQ;
    const size_t voff = (size_t)blockIdx.z * DIM * SEQ;
    float* C = out + (size_t)blockIdx.z * SEQ * DIM;
    gemm_pipe<3, 1>(g_Phi + poff, nullptr, SEQ, g_VThi + voff, SEQ,
                    C, nullptr, nullptr, DIM, i0, j0, i0 + 128, blockIdx.z * SEQ);
}

// ---------------- rowsum reduce (deterministic) ---------------------------------
__global__ void __launch_bounds__(256)
reduce_rowsum()
{
    const int i = blockIdx.x * 256 + threadIdx.x;   // global token row
    const int q = i & (SEQ - 1);
    const int nt = (q >> 7) + 1;                    // valid tiles for this row
    const float* p = g_partial + (size_t)i * 32;
    float s = 0.f;
    for (int t = 0; t < nt; ++t) s += p[t];
    g_rowsum[i] = s;
}

// ---------------- conversion / transpose kernels -------------------------------
__global__ void conv_x(const float* __restrict__ X)
{
    size_t i = (size_t)blockIdx.x * blockDim.x + threadIdx.x;
    const size_t n4 = (size_t)NTOK * DIM / 4;
    for (; i < n4; i += (size_t)gridDim.x * blockDim.x) {
        float4 v = reinterpret_cast<const float4*>(X)[i];
        uint32_t h0, l0, h1, l1;
        split2h(v.x, v.y, h0, l0);
        split2h(v.z, v.w, h1, l1);
        reinterpret_cast<uint2*>(g_Xhi)[i] = make_uint2(h0, h1);
        reinterpret_cast<uint2*>(g_Xlo)[i] = make_uint2(l0, l1);
    }
}

__global__ void transpose_w(const float* __restrict__ Wq,
                            const float* __restrict__ Wk,
                            const float* __restrict__ Wv)
{
    const float* src = (blockIdx.z == 0) ? Wq : (blockIdx.z == 1) ? Wk : Wv;
    __half* dh = g_WThi + (size_t)blockIdx.z * DIM * DIM;
    __shared__ float t[32][33];
    const int bx = blockIdx.x * 32, by = blockIdx.y * 32;
    const int tx = threadIdx.x, ty = threadIdx.y;
#pragma unroll
    for (int j = 0; j < 32; j += 8)
        t[ty + j][tx] = src[(size_t)(by + ty + j) * DIM + bx + tx];
    __syncthreads();
#pragma unroll
    for (int j = 0; j < 32; j += 8)
        dh[(size_t)(bx + ty + j) * DIM + by + tx] = h_hi(t[tx][ty + j]);
}

__global__ void transpose_v()
{
    const int b = blockIdx.z;
    const __half* sh = g_Vhi + (size_t)b * SEQ * DIM;
    const __half* sl = g_Vlo + (size_t)b * SEQ * DIM;
    __half* dh = g_VThi + (size_t)b * DIM * SEQ;
    __shared__ float t[32][33];
    const int bx = blockIdx.x * 32, by = blockIdx.y * 32;   // bx over DIM, by over SEQ
    const int tx = threadIdx.x, ty = threadIdx.y;
#pragma unroll
    for (int j = 0; j < 32; j += 8) {
        size_t idx = (size_t)(by + ty + j) * DIM + bx + tx;
        t[ty + j][tx] = __half2float(sh[idx]) + __half2float(sl[idx]);
    }
    __syncthreads();
#pragma unroll
    for (int j = 0; j < 32; j += 8)
        dh[(size_t)(bx + ty + j) * SEQ + by + tx] = h_hi(t[tx][ty + j]);
}

// ---------------- launch ---------------------------------------------------------
extern "C" void kernel_launch(void* const* d_in, const int* in_sizes, int n_in,
                              void* d_out, int out_size)
{
    const float* x  = (const float*)d_in[0];
    const float* Wq = (const float*)d_in[1];
    const float* Wk = (const float*)d_in[2];
    const float* Wv = (const float*)d_in[3];
    float* out = (float*)d_out;

    cudaFuncSetAttribute(proj_tc,   cudaFuncAttributeMaxDynamicSharedMemorySize, SMEM_BYTES);
    cudaFuncSetAttribute(scores_tc, cudaFuncAttributeMaxDynamicSharedMemorySize, SMEM_BYTES);
    cudaFuncSetAttribute(pv_tc,     cudaFuncAttributeMaxDynamicSharedMemorySize, SMEM_BYTES);

    dim3 t32(32, 8);
    conv_x<<<512, 256>>>(x);
    transpose_w<<<dim3(DIM / 32, DIM / 32, 3), t32>>>(Wq, Wk, Wv);
    proj_tc<<<dim3(DIM / 128, NTOK / 128, 3), 256, SMEM_BYTES>>>();
    transpose_v<<<dim3(DIM / 32, SEQ / 32, BATCH), t32>>>();
    scores_tc<<<dim3(SEQ / 128, SEQ / 128, BATCH), 256, SMEM_BYTES>>>();
    reduce_rowsum<<<NTOK / 256, 256>>>();
    pv_tc<<<dim3(DIM / 128, SEQ / 128, BATCH), 256, SMEM_BYTES>>>(out);
}

// round 11
// speedup vs baseline: 2.0686x; 1.1650x over previous
#include <cuda_runtime.h>
#include <cuda_fp16.h>
#include <cstdint>

#define BATCH 4
#define SEQ   4096
#define DIM   768
#define NTOK  (BATCH*SEQ)

// ---------------- scratch (__device__ globals: allocation-free rule) --------
__device__ __half g_Xhi [(size_t)NTOK * DIM];
__device__ __half g_Xlo [(size_t)NTOK * DIM];
__device__ __half g_WThi[3ull * DIM * DIM];               // B side: hi only
__device__ __half g_Qhi [(size_t)NTOK * DIM];
__device__ __half g_Qlo [(size_t)NTOK * DIM];
__device__ __half g_Khi [(size_t)NTOK * DIM];             // fp16 only (B side)
__device__ __half g_Vhi [(size_t)NTOK * DIM];             // fp16 only
__device__ __half g_VThi[(size_t)BATCH * DIM * SEQ];      // B side: hi only
__device__ __half g_Phi [(size_t)BATCH * SEQ * SEQ];      // exp(scores)/64, fp16
__device__ float g_partial[(size_t)NTOK * 32];            // per-(row,tile) sums
__device__ float g_rowsum [(size_t)NTOK];                 // final row sums

// ---------------- PTX helpers (arch-agnostic, sm_80-class) ------------------
__device__ __forceinline__ uint32_t smem_u32(const void* p) {
    uint32_t a;
    asm("{ .reg .u64 t; cvta.to.shared.u64 t, %1; cvt.u32.u64 %0, t; }"
        : "=r"(a) : "l"(p));
    return a;
}
__device__ __forceinline__ void cp16(uint32_t dst, const void* src) {
    asm volatile("cp.async.cg.shared.global [%0], [%1], 16;"
                 :: "r"(dst), "l"(src) : "memory");
}
#define CP_COMMIT() asm volatile("cp.async.commit_group;" ::: "memory")
#define CP_WAIT(N)  asm volatile("cp.async.wait_group %0;" :: "n"(N) : "memory")

__device__ __forceinline__ void ldsm_x4(uint32_t* r, uint32_t addr) {
    asm volatile("ldmatrix.sync.aligned.m8n8.x4.shared.b16 {%0,%1,%2,%3}, [%4];"
                 : "=r"(r[0]), "=r"(r[1]), "=r"(r[2]), "=r"(r[3]) : "r"(addr));
}
__device__ __forceinline__ void mma16816(float* d, const uint32_t* a, const uint32_t* b) {
    asm volatile(
        "mma.sync.aligned.m16n8k16.row.col.f32.f16.f16.f32 "
        "{%0,%1,%2,%3}, {%4,%5,%6,%7}, {%8,%9}, {%0,%1,%2,%3};"
        : "+f"(d[0]), "+f"(d[1]), "+f"(d[2]), "+f"(d[3])
        : "r"(a[0]), "r"(a[1]), "r"(a[2]), "r"(a[3]), "r"(b[0]), "r"(b[1]));
}

__device__ __forceinline__ void split2h(float a, float b, uint32_t& h, uint32_t& l) {
    __half2 hv = __floats2half2_rn(a, b);
    float2 f = __half22float2(hv);
    __half2 lv = __floats2half2_rn(a - f.x, b - f.y);
    h = *reinterpret_cast<uint32_t*>(&hv);
    l = *reinterpret_cast<uint32_t*>(&lv);
}
__device__ __forceinline__ uint32_t pack2h(float a, float b) {
    __half2 hv = __floats2half2_rn(a, b);
    return *reinterpret_cast<uint32_t*>(&hv);
}
__device__ __forceinline__ __half h_hi(float v) { return __float2half_rn(v); }

// ---------------- pipelined GEMM core ----------------------------------------
// C[128,128] = (Ahi[+Alo])[128,K] * Bhi[128,K]^T, fp16 MMA x NTERMS, fp32 accum.
// 256 threads, warp grid 4(m) x 2(n), warp tile 32x64, k-step 32, 2-stage cp.async.
// 4m x 2n layout: A (2 buffers) re-read x2 n-warps, B (1 buffer) x4 m-warps
// -> 20% less smem crossbar traffic than 2m x 4n for 2-term GEMMs.
#define LDSE 40                      // smem row stride (fp16): conflict-free ldsm
#define BUFB (128 * LDSE * 2)        // 10240 B per buffer
#define SMEM_BYTES (2 * 3 * BUFB)    // 61440 B (max: 3 buffers/stage)

#define SM_SCALE 0.03608439182435161f   // 1/sqrt(768)
#define P_SCALE  0.015625f              // store exp/64 (overflow headroom in fp16)

// MODE 1: write split fp16 Chi/Clo (proj Q).
// MODE 4: write fp16 Chi only (proj K/V).
// MODE 2: exp/64 + causal mask + per-row partial sums -> g_partial; fp16 out.
// MODE 3: write fp32 C scaled by 1/g_rowsum[row] (pv).
// NTERMS: 2 = A hi+lo (3 staged buffers), 1 = A hi only (2 staged buffers).
template <int MODE, int NTERMS>
__device__ __forceinline__ void gemm_pipe(
    const __half* __restrict__ Ahi, const __half* __restrict__ Alo, int lda,
    const __half* __restrict__ Bhi, int ldb,
    float* __restrict__ C, __half* __restrict__ Chi, __half* __restrict__ Clo,
    int ldc, int i0, int j0, int K, int rs_off)
{
    extern __shared__ __align__(16) uint16_t dsm[];
    const uint32_t sb = smem_u32(dsm);

    const int tid  = threadIdx.x;
    const int wid  = tid >> 5;
    const int lane = tid & 31;
    const int m0 = (wid & 3) * 32;       // 4 m-warps x 32 rows
    const int n0 = (wid >> 2) * 64;      // 2 n-warps x 64 cols

    const int a_row = lane & 15;
    const int a_col = (lane >> 4) * 8;
    const int b_row = ((lane >> 4) & 1) * 8 + (lane & 7);
    const int b_col = ((lane >> 3) & 1) * 8;

    const int r0 = tid >> 2,         c0 = (tid & 3) * 8;
    const int r1 = (tid + 256) >> 2, c1 = ((tid + 256) & 3) * 8;

    constexpr int NBUF = NTERMS + 1;                 // A bufs + 1 B buf
    const __half* gsrc[3] = {Ahi, (NTERMS == 2) ? Alo : Bhi, Bhi};
    const int glda[3] = {lda, (NTERMS == 2) ? lda : ldb, ldb};
    const int grow[3] = {i0, (NTERMS == 2) ? i0 : j0, j0};

    const int nk = K >> 5;

    auto stage = [&](int s, int kt) {
#pragma unroll
        for (int b = 0; b < NBUF; ++b) {
            uint32_t base = sb + (uint32_t)((s * NBUF + b) * BUFB);
            const __half* g = gsrc[b];
            cp16(base + (uint32_t)(r0 * LDSE + c0) * 2,
                 g + (size_t)(grow[b] + r0) * glda[b] + kt + c0);
            cp16(base + (uint32_t)(r1 * LDSE + c1) * 2,
                 g + (size_t)(grow[b] + r1) * glda[b] + kt + c1);
        }
        CP_COMMIT();
    };

    float acc[2][8][4] = {};

    stage(0, 0);
    for (int it = 0; it < nk; ++it) {
        const int s = it & 1;
        if (it + 1 < nk) {
            stage(s ^ 1, (it + 1) << 5);
            CP_WAIT(1);
        } else {
            CP_WAIT(0);
        }
        __syncthreads();

        const uint32_t bAhi = sb + (uint32_t)((s * NBUF + 0) * BUFB);
        const uint32_t bAlo = sb + (uint32_t)((s * NBUF + 1) * BUFB);       // NTERMS==2
        const uint32_t bBhi = sb + (uint32_t)((s * NBUF + NBUF - 1) * BUFB);

#pragma unroll
        for (int kk = 0; kk < 32; kk += 16) {
            uint32_t aH[2][4], aL[2][4];
#pragma unroll
            for (int mi = 0; mi < 2; ++mi) {
                uint32_t off = (uint32_t)((m0 + mi * 16 + a_row) * LDSE + kk + a_col) * 2;
                ldsm_x4(aH[mi], bAhi + off);
                if (NTERMS == 2) ldsm_x4(aL[mi], bAlo + off);
            }
#pragma unroll
            for (int nj = 0; nj < 4; ++nj) {         // 4 x 16-n chunks = 64 n
                uint32_t off = (uint32_t)((n0 + nj * 16 + b_row) * LDSE + kk + b_col) * 2;
                uint32_t bh[4];
                ldsm_x4(bh, bBhi + off);
#pragma unroll
                for (int mi = 0; mi < 2; ++mi) {
                    float* a0 = acc[mi][nj * 2];
                    float* a1 = acc[mi][nj * 2 + 1];
                    mma16816(a0, aH[mi], bh);
                    mma16816(a1, aH[mi], bh + 2);
                    if (NTERMS == 2) {
                        mma16816(a0, aL[mi], bh);
                        mma16816(a1, aL[mi], bh + 2);
                    }
                }
            }
        }
        __syncthreads();
    }

    // ---- epilogue ------------------------------------------------------------
    const int tr = lane >> 2;
    const int tc = (lane & 3) * 2;

    if (MODE == 1 || MODE == 4) {
#pragma unroll
        for (int mi = 0; mi < 2; ++mi)
#pragma unroll
            for (int nj = 0; nj < 8; ++nj) {
                int row = i0 + m0 + mi * 16 + tr;
                int col = j0 + n0 + nj * 8 + tc;
                size_t idx = (size_t)row * ldc + col;
                if (MODE == 1) {
                    uint32_t h, l;
                    split2h(acc[mi][nj][0], acc[mi][nj][1], h, l);
                    *reinterpret_cast<uint32_t*>(Chi + idx) = h;
                    *reinterpret_cast<uint32_t*>(Clo + idx) = l;
                    idx = (size_t)(row + 8) * ldc + col;
                    split2h(acc[mi][nj][2], acc[mi][nj][3], h, l);
                    *reinterpret_cast<uint32_t*>(Chi + idx) = h;
                    *reinterpret_cast<uint32_t*>(Clo + idx) = l;
                } else {
                    *reinterpret_cast<uint32_t*>(Chi + idx) =
                        pack2h(acc[mi][nj][0], acc[mi][nj][1]);
                    idx = (size_t)(row + 8) * ldc + col;
                    *reinterpret_cast<uint32_t*>(Chi + idx) =
                        pack2h(acc[mi][nj][2], acc[mi][nj][3]);
                }
            }
    } else if (MODE == 2) {
        float* red = reinterpret_cast<float*>(dsm);     // 128 rows x 2 n-warps
        const int nwid = wid >> 2;
#pragma unroll
        for (int mi = 0; mi < 2; ++mi) {
#pragma unroll
            for (int rp = 0; rp < 2; ++rp) {
                const int lrow = m0 + mi * 16 + tr + rp * 8;
                const int row  = i0 + lrow;
                float part = 0.f;
#pragma unroll
                for (int nj = 0; nj < 8; ++nj) {
                    int col = j0 + n0 + nj * 8 + tc;
                    float e0 = (col     <= row)
                        ? __expf(acc[mi][nj][rp * 2]     * SM_SCALE) * P_SCALE : 0.f;
                    float e1 = (col + 1 <= row)
                        ? __expf(acc[mi][nj][rp * 2 + 1] * SM_SCALE) * P_SCALE : 0.f;
                    size_t idx = (size_t)row * ldc + col;
                    *reinterpret_cast<uint32_t*>(Chi + idx) = pack2h(e0, e1);
                    part += e0 + e1;
                }
                part += __shfl_xor_sync(0xffffffffu, part, 1);
                part += __shfl_xor_sync(0xffffffffu, part, 2);
                if ((lane & 3) == 0) red[lrow * 2 + nwid] = part;
            }
        }
        __syncthreads();
        if (tid < 128) {
            float s = red[tid * 2] + red[tid * 2 + 1];
            g_partial[(size_t)(rs_off + i0 + tid) * 32 + (j0 >> 7)] = s;
        }
    } else {  // MODE 3: pv, normalize by row sums (both scaled by 1/64 -> cancels)
#pragma unroll
        for (int mi = 0; mi < 2; ++mi) {
            int row = i0 + m0 + mi * 16 + tr;
            float s0 = 1.0f / g_rowsum[rs_off + row];
            float s1 = 1.0f / g_rowsum[rs_off + row + 8];
#pragma unroll
            for (int nj = 0; nj < 8; ++nj) {
                int col = j0 + n0 + nj * 8 + tc;
                *reinterpret_cast<float2*>(C + (size_t)row * ldc + col) =
                    make_float2(acc[mi][nj][0] * s0, acc[mi][nj][1] * s0);
                *reinterpret_cast<float2*>(C + (size_t)(row + 8) * ldc + col) =
                    make_float2(acc[mi][nj][2] * s1, acc[mi][nj][3] * s1);
            }
        }
    }
}

// ---------------- GEMM stage kernels ------------------------------------------
__global__ void __launch_bounds__(256, 2)
proj_q_tc()
{
    gemm_pipe<1, 2>(g_Xhi, g_Xlo, DIM, g_WThi, DIM,
                    nullptr, g_Qhi, g_Qlo, DIM,
                    blockIdx.y * 128, blockIdx.x * 128, DIM, 0);
}

__global__ void __launch_bounds__(256, 2)
proj_kv_tc()
{
    const int z = blockIdx.z;                 // 0 = K, 1 = V
    const __half* Bh = g_WThi + (size_t)(z + 1) * DIM * DIM;
    __half* Ch = (z == 0) ? g_Khi : g_Vhi;
    gemm_pipe<4, 1>(g_Xhi, nullptr, DIM, Bh, DIM,
                    nullptr, Ch, nullptr, DIM,
                    blockIdx.y * 128, blockIdx.x * 128, DIM, 0);
}

__global__ void __launch_bounds__(256, 2)
scores_tc()
{
    const int i0 = blockIdx.y * 128, j0 = blockIdx.x * 128;
    if (j0 > i0) return;   // fully-masked causal tile
    const size_t off = (size_t)blockIdx.z * SEQ * DIM;
    __half* Ch = g_Phi + (size_t)blockIdx.z * SEQ * SEQ;
    gemm_pipe<2, 2>(g_Qhi + off, g_Qlo + off, DIM, g_Khi + off, DIM,
                    nullptr, Ch, nullptr, SEQ, i0, j0, DIM, blockIdx.z * SEQ);
}

__global__ void __launch_bounds__(256, 2)
pv_tc(float* __restrict__ out)
{
    const int i0 = blockIdx.y * 128, j0 = blockIdx.x * 128;
    const size_t poff = (size_t)blockIdx.z * SEQ * SEQ;
    const size_t voff = (size_t)blockIdx.z * DIM * SEQ;
    float* C = out + (size_t)blockIdx.z * SEQ * DIM;
    gemm_pipe<3, 1>(g_Phi + poff, nullptr, SEQ, g_VThi + voff, SEQ,
                    C, nullptr, nullptr, DIM, i0, j0, i0 + 128, blockIdx.z * SEQ);
}

// ---------------- rowsum reduce (deterministic) ---------------------------------
__global__ void __launch_bounds__(256)
reduce_rowsum()
{
    const int i = blockIdx.x * 256 + threadIdx.x;   // global token row
    const int q = i & (SEQ - 1);
    const int nt = (q >> 7) + 1;                    // valid tiles for this row
    const float* p = g_partial + (size_t)i * 32;
    float s = 0.f;
    for (int t = 0; t < nt; ++t) s += p[t];
    g_rowsum[i] = s;
}

// ---------------- conversion / transpose kernels -------------------------------
__global__ void conv_x(const float* __restrict__ X)
{
    size_t i = (size_t)blockIdx.x * blockDim.x + threadIdx.x;
    const size_t n4 = (size_t)NTOK * DIM / 4;
    for (; i < n4; i += (size_t)gridDim.x * blockDim.x) {
        float4 v = reinterpret_cast<const float4*>(X)[i];
        uint32_t h0, l0, h1, l1;
        split2h(v.x, v.y, h0, l0);
        split2h(v.z, v.w, h1, l1);
        reinterpret_cast<uint2*>(g_Xhi)[i] = make_uint2(h0, h1);
        reinterpret_cast<uint2*>(g_Xlo)[i] = make_uint2(l0, l1);
    }
}

__global__ void transpose_w(const float* __restrict__ Wq,
                            const float* __restrict__ Wk,
                            const float* __restrict__ Wv)
{
    const float* src = (blockIdx.z == 0) ? Wq : (blockIdx.z == 1) ? Wk : Wv;
    __half* dh = g_WThi + (size_t)blockIdx.z * DIM * DIM;
    __shared__ float t[32][33];
    const int bx = blockIdx.x * 32, by = blockIdx.y * 32;
    const int tx = threadIdx.x, ty = threadIdx.y;
#pragma unroll
    for (int j = 0; j < 32; j += 8)
        t[ty + j][tx] = src[(size_t)(by + ty + j) * DIM + bx + tx];
    __syncthreads();
#pragma unroll
    for (int j = 0; j < 32; j += 8)
        dh[(size_t)(bx + ty + j) * DIM + by + tx] = h_hi(t[tx][ty + j]);
}

__global__ void transpose_v()
{
    const int b = blockIdx.z;
    const __half* sh = g_Vhi + (size_t)b * SEQ * DIM;
    __half* dh = g_VThi + (size_t)b * DIM * SEQ;
    __shared__ __half t[32][34];
    const int bx = blockIdx.x * 32, by = blockIdx.y * 32;   // bx over DIM, by over SEQ
    const int tx = threadIdx.x, ty = threadIdx.y;
#pragma unroll
    for (int j = 0; j < 32; j += 8)
        t[ty + j][tx] = sh[(size_t)(by + ty + j) * DIM + bx + tx];
    __syncthreads();
#pragma unroll
    for (int j = 0; j < 32; j += 8)
        dh[(size_t)(bx + ty + j) * SEQ + by + tx] = t[tx][ty + j];
}

// ---------------- launch ---------------------------------------------------------
extern "C" void kernel_launch(void* const* d_in, const int* in_sizes, int n_in,
                              void* d_out, int out_size)
{
    const float* x  = (const float*)d_in[0];
    const float* Wq = (const float*)d_in[1];
    const float* Wk = (const float*)d_in[2];
    const float* Wv = (const float*)d_in[3];
    float* out = (float*)d_out;

    cudaFuncSetAttribute(proj_q_tc,  cudaFuncAttributeMaxDynamicSharedMemorySize, SMEM_BYTES);
    cudaFuncSetAttribute(proj_kv_tc, cudaFuncAttributeMaxDynamicSharedMemorySize, SMEM_BYTES);
    cudaFuncSetAttribute(scores_tc,  cudaFuncAttributeMaxDynamicSharedMemorySize, SMEM_BYTES);
    cudaFuncSetAttribute(pv_tc,      cudaFuncAttributeMaxDynamicSharedMemorySize, SMEM_BYTES);

    dim3 t32(32, 8);
    conv_x<<<512, 256>>>(x);
    transpose_w<<<dim3(DIM / 32, DIM / 32, 3), t32>>>(Wq, Wk, Wv);
    proj_q_tc<<<dim3(DIM / 128, NTOK / 128), 256, SMEM_BYTES>>>();
    proj_kv_tc<<<dim3(DIM / 128, NTOK / 128, 2), 256, SMEM_BYTES>>>();
    transpose_v<<<dim3(DIM / 32, SEQ / 32, BATCH), t32>>>();
    scores_tc<<<dim3(SEQ / 128, SEQ / 128, BATCH), 256, SMEM_BYTES>>>();
    reduce_rowsum<<<NTOK / 256, 256>>>();
    pv_tc<<<dim3(DIM / 128, SEQ / 128, BATCH), 256, SMEM_BYTES>>>(out);
}

// round 12
// speedup vs baseline: 2.2328x; 1.0794x over previous
#include <cuda_runtime.h>
#include <cuda_fp16.h>
#include <cstdint>

#define BATCH 4
#define SEQ   4096
#define DIM   768
#define NTOK  (BATCH*SEQ)

// ---------------- scratch (__device__ globals: allocation-free rule) --------
__device__ __half g_Xhi [(size_t)NTOK * DIM];
__device__ __half g_Xlo [(size_t)NTOK * DIM];
__device__ __half g_WThi[3ull * DIM * DIM];               // B side: hi only
__device__ __half g_Qhi [(size_t)NTOK * DIM];
__device__ __half g_Qlo [(size_t)NTOK * DIM];
__device__ __half g_Khi [(size_t)NTOK * DIM];             // fp16 only (B side)
__device__ __half g_Vhi [(size_t)NTOK * DIM];             // fp16 only
__device__ __half g_VThi[(size_t)BATCH * DIM * SEQ];      // B side: hi only
__device__ __half g_Phi [(size_t)BATCH * SEQ * SEQ];      // exp(scores)/64, fp16
__device__ float g_partial[(size_t)NTOK * 32];            // per-(row,tile) sums
__device__ float g_rowsum [(size_t)NTOK];                 // final row sums

// ---------------- PTX helpers (arch-agnostic, sm_80-class) ------------------
__device__ __forceinline__ uint32_t smem_u32(const void* p) {
    uint32_t a;
    asm("{ .reg .u64 t; cvta.to.shared.u64 t, %1; cvt.u32.u64 %0, t; }"
        : "=r"(a) : "l"(p));
    return a;
}
__device__ __forceinline__ void cp16(uint32_t dst, const void* src) {
    asm volatile("cp.async.cg.shared.global [%0], [%1], 16;"
                 :: "r"(dst), "l"(src) : "memory");
}
#define CP_COMMIT() asm volatile("cp.async.commit_group;" ::: "memory")
#define CP_WAIT(N)  asm volatile("cp.async.wait_group %0;" :: "n"(N) : "memory")

__device__ __forceinline__ void ldsm_x4(uint32_t* r, uint32_t addr) {
    asm volatile("ldmatrix.sync.aligned.m8n8.x4.shared.b16 {%0,%1,%2,%3}, [%4];"
                 : "=r"(r[0]), "=r"(r[1]), "=r"(r[2]), "=r"(r[3]) : "r"(addr));
}
__device__ __forceinline__ void mma16816(float* d, const uint32_t* a, const uint32_t* b) {
    asm volatile(
        "mma.sync.aligned.m16n8k16.row.col.f32.f16.f16.f32 "
        "{%0,%1,%2,%3}, {%4,%5,%6,%7}, {%8,%9}, {%0,%1,%2,%3};"
        : "+f"(d[0]), "+f"(d[1]), "+f"(d[2]), "+f"(d[3])
        : "r"(a[0]), "r"(a[1]), "r"(a[2]), "r"(a[3]), "r"(b[0]), "r"(b[1]));
}

__device__ __forceinline__ void split2h(float a, float b, uint32_t& h, uint32_t& l) {
    __half2 hv = __floats2half2_rn(a, b);
    float2 f = __half22float2(hv);
    __half2 lv = __floats2half2_rn(a - f.x, b - f.y);
    h = *reinterpret_cast<uint32_t*>(&hv);
    l = *reinterpret_cast<uint32_t*>(&lv);
}
__device__ __forceinline__ uint32_t pack2h(float a, float b) {
    __half2 hv = __floats2half2_rn(a, b);
    return *reinterpret_cast<uint32_t*>(&hv);
}
__device__ __forceinline__ __half h_hi(float v) { return __float2half_rn(v); }

// ---------------- pipelined GEMM core ----------------------------------------
// C[128,128] = (Ahi[+Alo])[128,K] * Bhi[128,K]^T, fp16 MMA x NTERMS, fp32 accum.
// 256 threads, warp grid 4(m) x 2(n), warp tile 32x64, k-step 64.
// 2-term: 2-stage x 3 buffers; 1-term: 3-stage x 2 buffers (both 110.6 KB/CTA,
// 2 CTAs/SM). LDSE=72 keeps the 16B/row bank rotation -> conflict-free ldsm.
#define LDSE 72                      // smem row stride (fp16) for k-step 64
#define BUFB (128 * LDSE * 2)        // 18432 B per buffer
#define SMEM_BYTES 110592            // = 2*3*BUFB = 3*2*BUFB

#define SM_SCALE 0.03608439182435161f   // 1/sqrt(768)
#define P_SCALE  0.015625f              // store exp/64 (overflow headroom in fp16)

// MODE 1: split fp16 Chi/Clo (proj Q). MODE 4: fp16 Chi only (proj K/V).
// MODE 2: exp/64 + causal mask + row partial sums -> g_partial; fp16 out.
// MODE 3: fp32 C scaled by 1/g_rowsum[row] (pv).
// NTERMS: 2 = A hi+lo, 1 = A hi only. NSTAGE: 2 for 2-term, 3 for 1-term.
template <int MODE, int NTERMS>
__device__ __forceinline__ void gemm_pipe(
    const __half* __restrict__ Ahi, const __half* __restrict__ Alo, int lda,
    const __half* __restrict__ Bhi, int ldb,
    float* __restrict__ C, __half* __restrict__ Chi, __half* __restrict__ Clo,
    int ldc, int i0, int j0, int K, int rs_off)
{
    extern __shared__ __align__(16) uint16_t dsm[];
    const uint32_t sb = smem_u32(dsm);

    const int tid  = threadIdx.x;
    const int wid  = tid >> 5;
    const int lane = tid & 31;
    const int m0 = (wid & 3) * 32;       // 4 m-warps x 32 rows
    const int n0 = (wid >> 2) * 64;      // 2 n-warps x 64 cols

    const int a_row = lane & 15;
    const int a_col = (lane >> 4) * 8;
    const int b_row = ((lane >> 4) & 1) * 8 + (lane & 7);
    const int b_col = ((lane >> 3) & 1) * 8;

    constexpr int NBUF   = NTERMS + 1;               // A bufs + 1 B buf
    constexpr int NSTAGE = (NTERMS == 2) ? 2 : 3;
    const __half* gsrc[3] = {Ahi, (NTERMS == 2) ? Alo : Bhi, Bhi};
    const int glda[3] = {lda, (NTERMS == 2) ? lda : ldb, ldb};
    const int grow[3] = {i0, (NTERMS == 2) ? i0 : j0, j0};

    const int nk = K >> 6;               // k-step 64

    auto stage = [&](int s, int kt) {
#pragma unroll
        for (int b = 0; b < NBUF; ++b) {
            uint32_t base = sb + (uint32_t)((s * NBUF + b) * BUFB);
            const __half* g = gsrc[b];
#pragma unroll
            for (int k = 0; k < 4; ++k) {            // 1024 chunks / 256 thr
                int u = tid + k * 256;
                int r = u >> 3, c = (u & 7) * 8;
                cp16(base + (uint32_t)(r * LDSE + c) * 2,
                     g + (size_t)(grow[b] + r) * glda[b] + kt + c);
            }
        }
        CP_COMMIT();
    };

    float acc[2][8][4] = {};

    stage(0, 0);
    if (NSTAGE == 3 && nk > 1) stage(1, 64);
    for (int it = 0; it < nk; ++it) {
        const int s = it % NSTAGE;
        if (it + NSTAGE - 1 < nk) {
            stage((it + NSTAGE - 1) % NSTAGE, (it + NSTAGE - 1) << 6);
            CP_WAIT(NSTAGE - 1);
        } else if (NSTAGE == 3 && it + 2 == nk) {
            CP_WAIT(1);
        } else {
            CP_WAIT(0);
        }
        __syncthreads();

        const uint32_t bAhi = sb + (uint32_t)((s * NBUF + 0) * BUFB);
        const uint32_t bAlo = sb + (uint32_t)((s * NBUF + 1) * BUFB);       // NTERMS==2
        const uint32_t bBhi = sb + (uint32_t)((s * NBUF + NBUF - 1) * BUFB);

#pragma unroll
        for (int kk = 0; kk < 64; kk += 16) {
            uint32_t aH[2][4], aL[2][4];
#pragma unroll
            for (int mi = 0; mi < 2; ++mi) {
                uint32_t off = (uint32_t)((m0 + mi * 16 + a_row) * LDSE + kk + a_col) * 2;
                ldsm_x4(aH[mi], bAhi + off);
                if (NTERMS == 2) ldsm_x4(aL[mi], bAlo + off);
            }
#pragma unroll
            for (int nj = 0; nj < 4; ++nj) {         // 4 x 16-n chunks = 64 n
                uint32_t off = (uint32_t)((n0 + nj * 16 + b_row) * LDSE + kk + b_col) * 2;
                uint32_t bh[4];
                ldsm_x4(bh, bBhi + off);
#pragma unroll
                for (int mi = 0; mi < 2; ++mi) {
                    float* a0 = acc[mi][nj * 2];
                    float* a1 = acc[mi][nj * 2 + 1];
                    mma16816(a0, aH[mi], bh);
                    mma16816(a1, aH[mi], bh + 2);
                    if (NTERMS == 2) {
                        mma16816(a0, aL[mi], bh);
                        mma16816(a1, aL[mi], bh + 2);
                    }
                }
            }
        }
        __syncthreads();
    }

    // ---- epilogue ------------------------------------------------------------
    const int tr = lane >> 2;
    const int tc = (lane & 3) * 2;

    if (MODE == 1 || MODE == 4) {
#pragma unroll
        for (int mi = 0; mi < 2; ++mi)
#pragma unroll
            for (int nj = 0; nj < 8; ++nj) {
                int row = i0 + m0 + mi * 16 + tr;
                int col = j0 + n0 + nj * 8 + tc;
                size_t idx = (size_t)row * ldc + col;
                if (MODE == 1) {
                    uint32_t h, l;
                    split2h(acc[mi][nj][0], acc[mi][nj][1], h, l);
                    *reinterpret_cast<uint32_t*>(Chi + idx) = h;
                    *reinterpret_cast<uint32_t*>(Clo + idx) = l;
                    idx = (size_t)(row + 8) * ldc + col;
                    split2h(acc[mi][nj][2], acc[mi][nj][3], h, l);
                    *reinterpret_cast<uint32_t*>(Chi + idx) = h;
                    *reinterpret_cast<uint32_t*>(Clo + idx) = l;
                } else {
                    *reinterpret_cast<uint32_t*>(Chi + idx) =
                        pack2h(acc[mi][nj][0], acc[mi][nj][1]);
                    idx = (size_t)(row + 8) * ldc + col;
                    *reinterpret_cast<uint32_t*>(Chi + idx) =
                        pack2h(acc[mi][nj][2], acc[mi][nj][3]);
                }
            }
    } else if (MODE == 2) {
        float* red = reinterpret_cast<float*>(dsm);     // 128 rows x 2 n-warps
        const int nwid = wid >> 2;
#pragma unroll
        for (int mi = 0; mi < 2; ++mi) {
#pragma unroll
            for (int rp = 0; rp < 2; ++rp) {
                const int lrow = m0 + mi * 16 + tr + rp * 8;
                const int row  = i0 + lrow;
                float part = 0.f;
#pragma unroll
                for (int nj = 0; nj < 8; ++nj) {
                    int col = j0 + n0 + nj * 8 + tc;
                    float e0 = (col     <= row)
                        ? __expf(acc[mi][nj][rp * 2]     * SM_SCALE) * P_SCALE : 0.f;
                    float e1 = (col + 1 <= row)
                        ? __expf(acc[mi][nj][rp * 2 + 1] * SM_SCALE) * P_SCALE : 0.f;
                    size_t idx = (size_t)row * ldc + col;
                    *reinterpret_cast<uint32_t*>(Chi + idx) = pack2h(e0, e1);
                    part += e0 + e1;
                }
                part += __shfl_xor_sync(0xffffffffu, part, 1);
                part += __shfl_xor_sync(0xffffffffu, part, 2);
                if ((lane & 3) == 0) red[lrow * 2 + nwid] = part;
            }
        }
        __syncthreads();
        if (tid < 128) {
            float s = red[tid * 2] + red[tid * 2 + 1];
            g_partial[(size_t)(rs_off + i0 + tid) * 32 + (j0 >> 7)] = s;
        }
    } else {  // MODE 3: pv, normalize by row sums (both scaled by 1/64 -> cancels)
#pragma unroll
        for (int mi = 0; mi < 2; ++mi) {
            int row = i0 + m0 + mi * 16 + tr;
            float s0 = 1.0f / g_rowsum[rs_off + row];
            float s1 = 1.0f / g_rowsum[rs_off + row + 8];
#pragma unroll
            for (int nj = 0; nj < 8; ++nj) {
                int col = j0 + n0 + nj * 8 + tc;
                *reinterpret_cast<float2*>(C + (size_t)row * ldc + col) =
                    make_float2(acc[mi][nj][0] * s0, acc[mi][nj][1] * s0);
                *reinterpret_cast<float2*>(C + (size_t)(row + 8) * ldc + col) =
                    make_float2(acc[mi][nj][2] * s1, acc[mi][nj][3] * s1);
            }
        }
    }
}

// ---------------- GEMM stage kernels ------------------------------------------
__global__ void __launch_bounds__(256, 2)
proj_q_tc()
{
    gemm_pipe<1, 2>(g_Xhi, g_Xlo, DIM, g_WThi, DIM,
                    nullptr, g_Qhi, g_Qlo, DIM,
                    blockIdx.y * 128, blockIdx.x * 128, DIM, 0);
}

__global__ void __launch_bounds__(256, 2)
proj_kv_tc()
{
    const int z = blockIdx.z;                 // 0 = K, 1 = V
    const __half* Bh = g_WThi + (size_t)(z + 1) * DIM * DIM;
    __half* Ch = (z == 0) ? g_Khi : g_Vhi;
    gemm_pipe<4, 1>(g_Xhi, nullptr, DIM, Bh, DIM,
                    nullptr, Ch, nullptr, DIM,
                    blockIdx.y * 128, blockIdx.x * 128, DIM, 0);
}

__global__ void __launch_bounds__(256, 2)
scores_tc()
{
    const int i0 = blockIdx.y * 128, j0 = blockIdx.x * 128;
    if (j0 > i0) return;   // fully-masked causal tile
    const size_t off = (size_t)blockIdx.z * SEQ * DIM;
    __half* Ch = g_Phi + (size_t)blockIdx.z * SEQ * SEQ;
    gemm_pipe<2, 2>(g_Qhi + off, g_Qlo + off, DIM, g_Khi + off, DIM,
                    nullptr, Ch, nullptr, SEQ, i0, j0, DIM, blockIdx.z * SEQ);
}

__global__ void __launch_bounds__(256, 2)
pv_tc(float* __restrict__ out)
{
    const int i0 = blockIdx.y * 128, j0 = blockIdx.x * 128;
    const size_t poff = (size_t)blockIdx.z * SEQ * SEQ;
    const size_t voff = (size_t)blockIdx.z * DIM * SEQ;
    float* C = out + (size_t)blockIdx.z * SEQ * DIM;
    gemm_pipe<3, 1>(g_Phi + poff, nullptr, SEQ, g_VThi + voff, SEQ,
                    C, nullptr, nullptr, DIM, i0, j0, i0 + 128, blockIdx.z * SEQ);
}

// ---------------- rowsum reduce (deterministic) ---------------------------------
__global__ void __launch_bounds__(256)
reduce_rowsum()
{
    const int i = blockIdx.x * 256 + threadIdx.x;   // global token row
    const int q = i & (SEQ - 1);
    const int nt = (q >> 7) + 1;                    // valid tiles for this row
    const float* p = g_partial + (size_t)i * 32;
    float s = 0.f;
    for (int t = 0; t < nt; ++t) s += p[t];
    g_rowsum[i] = s;
}

// ---------------- conversion / transpose kernels -------------------------------
__global__ void conv_x(const float* __restrict__ X)
{
    size_t i = (size_t)blockIdx.x * blockDim.x + threadIdx.x;
    const size_t n4 = (size_t)NTOK * DIM / 4;
    for (; i < n4; i += (size_t)gridDim.x * blockDim.x) {
        float4 v = reinterpret_cast<const float4*>(X)[i];
        uint32_t h0, l0, h1, l1;
        split2h(v.x, v.y, h0, l0);
        split2h(v.z, v.w, h1, l1);
        reinterpret_cast<uint2*>(g_Xhi)[i] = make_uint2(h0, h1);
        reinterpret_cast<uint2*>(g_Xlo)[i] = make_uint2(l0, l1);
    }
}

__global__ void transpose_w(const float* __restrict__ Wq,
                            const float* __restrict__ Wk,
                            const float* __restrict__ Wv)
{
    const float* src = (blockIdx.z == 0) ? Wq : (blockIdx.z == 1) ? Wk : Wv;
    __half* dh = g_WThi + (size_t)blockIdx.z * DIM * DIM;
    __shared__ float t[32][33];
    const int bx = blockIdx.x * 32, by = blockIdx.y * 32;
    const int tx = threadIdx.x, ty = threadIdx.y;
#pragma unroll
    for (int j = 0; j < 32; j += 8)
        t[ty + j][tx] = src[(size_t)(by + ty + j) * DIM + bx + tx];
    __syncthreads();
#pragma unroll
    for (int j = 0; j < 32; j += 8)
        dh[(size_t)(bx + ty + j) * DIM + by + tx] = h_hi(t[tx][ty + j]);
}

__global__ void transpose_v()
{
    const int b = blockIdx.z;
    const __half* sh = g_Vhi + (size_t)b * SEQ * DIM;
    __half* dh = g_VThi + (size_t)b * DIM * SEQ;
    __shared__ __half t[32][34];
    const int bx = blockIdx.x * 32, by = blockIdx.y * 32;   // bx over DIM, by over SEQ
    const int tx = threadIdx.x, ty = threadIdx.y;
#pragma unroll
    for (int j = 0; j < 32; j += 8)
        t[ty + j][tx] = sh[(size_t)(by + ty + j) * DIM + bx + tx];
    __syncthreads();
#pragma unroll
    for (int j = 0; j < 32; j += 8)
        dh[(size_t)(bx + ty + j) * SEQ + by + tx] = t[tx][ty + j];
}

// ---------------- launch ---------------------------------------------------------
extern "C" void kernel_launch(void* const* d_in, const int* in_sizes, int n_in,
                              void* d_out, int out_size)
{
    const float* x  = (const float*)d_in[0];
    const float* Wq = (const float*)d_in[1];
    const float* Wk = (const float*)d_in[2];
    const float* Wv = (const float*)d_in[3];
    float* out = (float*)d_out;

    cudaFuncSetAttribute(proj_q_tc,  cudaFuncAttributeMaxDynamicSharedMemorySize, SMEM_BYTES);
    cudaFuncSetAttribute(proj_kv_tc, cudaFuncAttributeMaxDynamicSharedMemorySize, SMEM_BYTES);
    cudaFuncSetAttribute(scores_tc,  cudaFuncAttributeMaxDynamicSharedMemorySize, SMEM_BYTES);
    cudaFuncSetAttribute(pv_tc,      cudaFuncAttributeMaxDynamicSharedMemorySize, SMEM_BYTES);

    dim3 t32(32, 8);
    conv_x<<<512, 256>>>(x);
    transpose_w<<<dim3(DIM / 32, DIM / 32, 3), t32>>>(Wq, Wk, Wv);
    proj_q_tc<<<dim3(DIM / 128, NTOK / 128), 256, SMEM_BYTES>>>();
    proj_kv_tc<<<dim3(DIM / 128, NTOK / 128, 2), 256, SMEM_BYTES>>>();
    transpose_v<<<dim3(DIM / 32, SEQ / 32, BATCH), t32>>>();
    scores_tc<<<dim3(SEQ / 128, SEQ / 128, BATCH), 256, SMEM_BYTES>>>();
    reduce_rowsum<<<NTOK / 256, 256>>>();
    pv_tc<<<dim3(DIM / 128, SEQ / 128, BATCH), 256, SMEM_BYTES>>>(out);
}